// round 13
// baseline (speedup 1.0000x reference)
#include <cuda_runtime.h>
#include <cuda_bf16.h>
#include <math.h>
#include <stdint.h>

// Problem constants
constexpr int B_  = 4;
constexpr int T_  = 2048;
constexpr int C_  = 1024;
constexpr int H_  = 16;
constexpr int HD  = 64;
constexpr int M_  = B_ * T_;

// -------------------- scratch (static device allocations) --------------------
// GEMM operands + K + V^T all use the K-CHUNK-TILED, PRE-SWIZZLED layout:
//   element (row, k) -> ((k/32)*NROWS + row)*32 + (((k>>3)&3) ^ ((row>>1)&3))*8 + (k&7)
__device__ __nv_bfloat16 g_ahi[M_ * C_];     // activations (x, later attn-out)
__device__ __nv_bfloat16 g_alo[M_ * C_];
__device__ __nv_bfloat16 g_whi[4 * C_ * C_]; // weights (q,k,v,o)
__device__ __nv_bfloat16 g_wlo[4 * C_ * C_];
__device__ __nv_bfloat16 g_qhi[B_ * H_ * T_ * HD];  // [B,H,T,hd] plain
__device__ __nv_bfloat16 g_qlo[B_ * H_ * T_ * HD];
__device__ __nv_bfloat16 g_khi[B_ * H_ * T_ * HD];  // per-bh tiled: rows=T, k=hd
__device__ __nv_bfloat16 g_klo[B_ * H_ * T_ * HD];
__device__ __nv_bfloat16 g_vthi[B_ * H_ * HD * T_]; // per-bh tiled: rows=hd, k=T
__device__ __nv_bfloat16 g_vtlo[B_ * H_ * HD * T_];

// =============================================================================
// helpers (compute_103-portable)
// =============================================================================
__device__ __forceinline__ uint32_t smem_u32(const void* p) {
    uint32_t a;
    asm("{ .reg .u64 t; cvta.to.shared.u64 t, %1; cvt.u32.u64 %0, t; }"
        : "=r"(a) : "l"(p));
    return a;
}
__device__ __forceinline__ void ldsm_x4(uint32_t addr, uint32_t* r) {
    asm volatile("ldmatrix.sync.aligned.m8n8.x4.shared.b16 {%0,%1,%2,%3}, [%4];"
                 : "=r"(r[0]), "=r"(r[1]), "=r"(r[2]), "=r"(r[3]) : "r"(addr));
}
__device__ __forceinline__ void mma_bf16(float* d, const uint32_t* a, const uint32_t* b) {
    asm volatile(
        "mma.sync.aligned.m16n8k16.row.col.f32.bf16.bf16.f32 "
        "{%0,%1,%2,%3}, {%4,%5,%6,%7}, {%8,%9}, {%0,%1,%2,%3};"
        : "+f"(d[0]), "+f"(d[1]), "+f"(d[2]), "+f"(d[3])
        : "r"(a[0]), "r"(a[1]), "r"(a[2]), "r"(a[3]), "r"(b[0]), "r"(b[1]));
}
__device__ __forceinline__ void cp_async16(uint32_t dst, const void* src) {
    asm volatile("cp.async.cg.shared.global [%0], [%1], 16;" :: "r"(dst), "l"(src));
}
#define CP_ASYNC_COMMIT() asm volatile("cp.async.commit_group;" ::: "memory")
#define CP_ASYNC_WAIT(n)  asm volatile("cp.async.wait_group %0;" :: "n"(n) : "memory")

// TMA 1D bulk copy global->shared with mbarrier completion
__device__ __forceinline__ void bulk_g2s(uint32_t dst, const void* src,
                                         uint32_t bytes, uint32_t mbar) {
    asm volatile(
        "cp.async.bulk.shared::cluster.global.mbarrier::complete_tx::bytes "
        "[%0], [%1], %2, [%3];"
        :: "r"(dst), "l"(src), "r"(bytes), "r"(mbar) : "memory");
}
#define MBARRIER_INIT(mbar, count) \
    asm volatile("mbarrier.init.shared.b64 [%0], %1;" \
                 :: "r"((uint32_t)(mbar)), "r"((uint32_t)(count)) : "memory")
#define MBARRIER_EXPECT_TX(mbar, bytes) \
    asm volatile("mbarrier.arrive.expect_tx.shared.b64 _, [%0], %1;" \
                 :: "r"((uint32_t)(mbar)), "r"((uint32_t)(bytes)) : "memory")
#define MBARRIER_WAIT_PARITY(mbar_addr, phase_parity) do { \
    uint32_t _mbar = (uint32_t)(mbar_addr); \
    uint32_t _parity = (uint32_t)(phase_parity); \
    uint32_t _done; \
    asm volatile( \
        "{\n\t.reg .pred p;\n\t" \
        "mbarrier.try_wait.parity.acquire.cta.shared::cta.b64 p, [%1], %2;\n\t" \
        "selp.b32 %0, 1, 0, p;\n\t}" \
        : "=r"(_done) : "r"(_mbar), "r"(_parity) : "memory"); \
    if (!_done) { \
        asm volatile( \
            "{\n\t.reg .pred P1;\n\t" \
            "WAIT_LOOP_%=:\n\t" \
            "mbarrier.try_wait.parity.acquire.cta.shared::cta.b64 P1, [%0], %1, 0x989680;\n\t" \
            "@P1 bra.uni WAIT_DONE_%=;\n\t" \
            "bra.uni WAIT_LOOP_%=;\n\t" \
            "WAIT_DONE_%=:\n\t}" \
            :: "r"(_mbar), "r"(_parity) : "memory"); \
    } \
} while (0)

__device__ __forceinline__ float ex2f(float x) {
    float y;
    asm("ex2.approx.ftz.f32 %0, %1;" : "=f"(y) : "f"(x));
    return y;
}
// pack (x,y) -> bf16x2 hi + bf16x2 lo residual
__device__ __forceinline__ void psplit(float x, float y, uint32_t& hi, uint32_t& lo) {
    __nv_bfloat162 h = __floats2bfloat162_rn(x, y);
    float rx = x - __bfloat162float(h.x);
    float ry = y - __bfloat162float(h.y);
    __nv_bfloat162 l = __floats2bfloat162_rn(rx, ry);
    hi = *(uint32_t*)&h;
    lo = *(uint32_t*)&l;
}

// tiled-layout element offset
__device__ __forceinline__ size_t tiled_off(int nrows, int row, int k) {
    int tk = k >> 5;
    int c  = (k >> 3) & 3;
    int cs = c ^ ((row >> 1) & 3);
    return ((size_t)(tk * nrows + row)) * 32 + cs * 8 + (k & 7);
}

// =============================================================================
// fused split: fp32 -> bf16 hi+lo, written into the tiled GEMM layout.
// =============================================================================
__global__ __launch_bounds__(256) void split_all(
    const float* __restrict__ x,
    const float* __restrict__ wq, const float* __restrict__ wk,
    const float* __restrict__ wv, const float* __restrict__ wo,
    __nv_bfloat16* __restrict__ ahi, __nv_bfloat16* __restrict__ alo,
    __nv_bfloat16* __restrict__ whi, __nv_bfloat16* __restrict__ wlo)
{
    const int nW = C_ * C_;
    int blk = blockIdx.x;
    const float* src;
    __nv_bfloat16 *hi, *lo;
    int base, nrows;
    if (blk < 8192) {
        src = x; hi = ahi; lo = alo; base = blk; nrows = 8192;
    } else {
        int r = blk - 8192;
        int ws = r >> 10;
        base = r & 1023;
        src = (ws == 0) ? wq : (ws == 1) ? wk : (ws == 2) ? wv : wo;
        hi = whi + (size_t)ws * nW;
        lo = wlo + (size_t)ws * nW;
        nrows = 1024;
    }
    int i = (base * 256 + threadIdx.x) * 4;
    int row = i >> 10;
    int k   = i & 1023;
    float4 v = *(const float4*)(src + i);
    uint32_t h0, l0, h1, l1;
    psplit(v.x, v.y, h0, l0);
    psplit(v.z, v.w, h1, l1);
    size_t off = tiled_off(nrows, row, k);
    *(uint32_t*)(hi + off)     = h0;
    *(uint32_t*)(hi + off + 2) = h1;
    *(uint32_t*)(lo + off)     = l0;
    *(uint32_t*)(lo + off + 2) = l1;
}

// =============================================================================
// GEMM mainloop (3-stage TMA bulk pipeline)
// =============================================================================
constexpr int TILE_B      = 128 * 64;                // 8192 bytes per operand tile
constexpr int STAGE_BYTES = 4 * TILE_B;              // 32768
constexpr int GEMM_SMEM   = 3 * STAGE_BYTES + 64;    // 3 stages + mbarriers

__device__ __forceinline__ void gemm_issue_stage(
    uint32_t st, uint32_t mbar,
    const __nv_bfloat16* __restrict__ Ahi, const __nv_bfloat16* __restrict__ Alo,
    const __nv_bfloat16* __restrict__ Whi, const __nv_bfloat16* __restrict__ Wlo,
    int bm, int bn, int tk)
{
    MBARRIER_EXPECT_TX(mbar, STAGE_BYTES);
    bulk_g2s(st,              Ahi + (size_t)(tk * 8192 + bm) * 32, TILE_B, mbar);
    bulk_g2s(st + TILE_B,     Alo + (size_t)(tk * 8192 + bm) * 32, TILE_B, mbar);
    bulk_g2s(st + 2 * TILE_B, Whi + (size_t)(tk * 1024 + bn) * 32, TILE_B, mbar);
    bulk_g2s(st + 3 * TILE_B, Wlo + (size_t)(tk * 1024 + bn) * 32, TILE_B, mbar);
}

__device__ __forceinline__ void gemm_mainloop(
    uint32_t sbase,
    const __nv_bfloat16* __restrict__ Ahi, const __nv_bfloat16* __restrict__ Alo,
    const __nv_bfloat16* __restrict__ Whi, const __nv_bfloat16* __restrict__ Wlo,
    int bm, int bn, int tid, float acc[2][8][4])
{
    const int lane = tid & 31;
    const int w    = tid >> 5;
    const int wm0  = (w & 3) * 32;
    const int wn0  = (w >> 2) * 64;
    constexpr int NC = C_ / 32;

    const uint32_t mbB = sbase + 3 * STAGE_BYTES;

    if (tid == 0) {
        MBARRIER_INIT(mbB + 0, 1);
        MBARRIER_INIT(mbB + 8, 1);
        MBARRIER_INIT(mbB + 16, 1);
    }
    __syncthreads();

    // prologue: chunks 0 and 1 into stages 0, 1
    if (tid == 0) {
        gemm_issue_stage(sbase,               mbB + 0, Ahi, Alo, Whi, Wlo, bm, bn, 0);
        gemm_issue_stage(sbase + STAGE_BYTES, mbB + 8, Ahi, Alo, Whi, Wlo, bm, bn, 1);
    }

    int ph[3] = {0, 0, 0};
    int s = 0;

    for (int ck = 0; ck < NC; ck++) {
        MBARRIER_WAIT_PARITY(mbB + s * 8, ph[s]);
        ph[s] ^= 1;
        __syncthreads();   // all warps finished reading stage (s+2)%3 (iter ck-1)

        if (ck + 2 < NC && tid == 0) {
            int s2 = s - 1; if (s2 < 0) s2 += 3;   // (ck+2)%3
            gemm_issue_stage(sbase + (uint32_t)s2 * STAGE_BYTES, mbB + s2 * 8,
                             Ahi, Alo, Whi, Wlo, bm, bn, ck + 2);
        }

        const uint32_t st  = sbase + (uint32_t)s * STAGE_BYTES;
        const uint32_t sAh = st;
        const uint32_t sAl = st + TILE_B;
        const uint32_t sWh = st + 2 * TILE_B;
        const uint32_t sWl = st + 3 * TILE_B;

        #pragma unroll
        for (int kk = 0; kk < 2; kk++) {
            uint32_t ah[2][4], al[2][4];
            #pragma unroll
            for (int mi = 0; mi < 2; mi++) {
                int r = wm0 + mi * 16 + (lane & 15);
                int c = kk * 2 + (lane >> 4);
                uint32_t off = (uint32_t)(r * 64 + ((c ^ ((r >> 1) & 3)) << 4));
                ldsm_x4(sAh + off, ah[mi]);
                ldsm_x4(sAl + off, al[mi]);
            }
            #pragma unroll
            for (int p = 0; p < 4; p++) {
                int r = wn0 + p * 16 + (lane & 7) + ((lane >> 4) & 1) * 8;
                int c = kk * 2 + ((lane >> 3) & 1);
                uint32_t off = (uint32_t)(r * 64 + ((c ^ ((r >> 1) & 3)) << 4));
                uint32_t wh[4], wl[4];
                ldsm_x4(sWh + off, wh);
                ldsm_x4(sWl + off, wl);
                #pragma unroll
                for (int mi = 0; mi < 2; mi++) {
                    mma_bf16(acc[mi][2 * p],     ah[mi], wh + 0);
                    mma_bf16(acc[mi][2 * p + 1], ah[mi], wh + 2);
                    mma_bf16(acc[mi][2 * p],     ah[mi], wl + 0);
                    mma_bf16(acc[mi][2 * p + 1], ah[mi], wl + 2);
                    mma_bf16(acc[mi][2 * p],     al[mi], wh + 0);
                    mma_bf16(acc[mi][2 * p + 1], al[mi], wh + 2);
                }
            }
        }
        s = (s == 2) ? 0 : s + 1;
    }
    __syncthreads();
}

// ---------- fused QKV projection: z selects {q,k,v} ----------
__global__ __launch_bounds__(256, 2) void gemm_qkv(
    const __nv_bfloat16* __restrict__ Ahi, const __nv_bfloat16* __restrict__ Alo,
    const __nv_bfloat16* __restrict__ Wh,  const __nv_bfloat16* __restrict__ Wl,
    const float* __restrict__ b0, const float* __restrict__ b1,
    const float* __restrict__ b2,
    __nv_bfloat16* __restrict__ qh, __nv_bfloat16* __restrict__ ql,
    __nv_bfloat16* __restrict__ kh, __nv_bfloat16* __restrict__ kl,
    __nv_bfloat16* __restrict__ vh, __nv_bfloat16* __restrict__ vl)
{
    extern __shared__ __align__(1024) char smem[];
    const uint32_t sbase = smem_u32(smem);
    const int tid = threadIdx.x;
    const int bm  = blockIdx.y * 128;
    const int bn  = blockIdx.x * 128;
    const int z   = blockIdx.z;
    const int nW  = C_ * C_;

    const float* bias = (z == 0) ? b0 : (z == 1) ? b1 : b2;

    float acc[2][8][4];
    #pragma unroll
    for (int mi = 0; mi < 2; mi++)
        #pragma unroll
        for (int ni = 0; ni < 8; ni++)
            #pragma unroll
            for (int t = 0; t < 4; t++) acc[mi][ni][t] = 0.f;

    gemm_mainloop(sbase, Ahi, Alo, Wh + (size_t)z * nW, Wl + (size_t)z * nW,
                  bm, bn, tid, acc);

    const int lane = tid & 31;
    const int w    = tid >> 5;
    const int wm0  = (w & 3) * 32;
    const int wn0  = (w >> 2) * 64;

    #pragma unroll
    for (int mi = 0; mi < 2; mi++) {
        #pragma unroll
        for (int ni = 0; ni < 8; ni++) {
            int row0 = bm + wm0 + mi * 16 + (lane >> 2);
            int col  = bn + wn0 + ni * 8 + (lane & 3) * 2;
            float bb0 = bias[col], bb1 = bias[col + 1];
            float v00 = acc[mi][ni][0] + bb0, v01 = acc[mi][ni][1] + bb1;
            float v10 = acc[mi][ni][2] + bb0, v11 = acc[mi][ni][3] + bb1;
            int h = col >> 6, d = col & 63;
            if (z == 0) {   // Q plain [B,H,T,hd]
                uint32_t hh, ll;
                {
                    int b = row0 >> 11, t = row0 & 2047;
                    size_t o = ((size_t)((b * H_ + h) * T_ + t)) * HD + d;
                    psplit(v00, v01, hh, ll);
                    *(uint32_t*)(qh + o) = hh; *(uint32_t*)(ql + o) = ll;
                }
                {
                    int r1 = row0 + 8;
                    int b = r1 >> 11, t = r1 & 2047;
                    size_t o = ((size_t)((b * H_ + h) * T_ + t)) * HD + d;
                    psplit(v10, v11, hh, ll);
                    *(uint32_t*)(qh + o) = hh; *(uint32_t*)(ql + o) = ll;
                }
            } else if (z == 1) {   // K tiled per bh: rows=T, k=hd
                uint32_t hh, ll;
                {
                    int b = row0 >> 11, t = row0 & 2047;
                    size_t o = (size_t)(b * H_ + h) * T_ * HD + tiled_off(T_, t, d);
                    psplit(v00, v01, hh, ll);
                    *(uint32_t*)(kh + o) = hh; *(uint32_t*)(kl + o) = ll;
                }
                {
                    int r1 = row0 + 8;
                    int b = r1 >> 11, t = r1 & 2047;
                    size_t o = (size_t)(b * H_ + h) * T_ * HD + tiled_off(T_, t, d);
                    psplit(v10, v11, hh, ll);
                    *(uint32_t*)(kh + o) = hh; *(uint32_t*)(kl + o) = ll;
                }
            } else {       // V^T tiled per bh: rows=hd, k=T
                int b = row0 >> 11, t = row0 & 2047;
                size_t bb = (size_t)(b * H_ + h) * HD * T_;
                __nv_bfloat16 h00 = __float2bfloat16_rn(v00);
                __nv_bfloat16 h01 = __float2bfloat16_rn(v01);
                __nv_bfloat16 h10 = __float2bfloat16_rn(v10);
                __nv_bfloat16 h11 = __float2bfloat16_rn(v11);
                size_t o00 = bb + tiled_off(HD, d,     t);
                size_t o01 = bb + tiled_off(HD, d + 1, t);
                size_t o10 = bb + tiled_off(HD, d,     t + 8);
                size_t o11 = bb + tiled_off(HD, d + 1, t + 8);
                vh[o00] = h00; vh[o01] = h01; vh[o10] = h10; vh[o11] = h11;
                vl[o00] = __float2bfloat16_rn(v00 - __bfloat162float(h00));
                vl[o01] = __float2bfloat16_rn(v01 - __bfloat162float(h01));
                vl[o10] = __float2bfloat16_rn(v10 - __bfloat162float(h10));
                vl[o11] = __float2bfloat16_rn(v11 - __bfloat162float(h11));
            }
        }
    }
}

// ---------- O-projection: fp32 row-major output ----------
__global__ __launch_bounds__(256, 2) void gemm_out(
    const __nv_bfloat16* __restrict__ Ahi, const __nv_bfloat16* __restrict__ Alo,
    const __nv_bfloat16* __restrict__ Whi, const __nv_bfloat16* __restrict__ Wlo,
    const float* __restrict__ bias, float* __restrict__ out)
{
    extern __shared__ __align__(1024) char smem[];
    const uint32_t sbase = smem_u32(smem);
    const int tid = threadIdx.x;
    const int bm  = blockIdx.y * 128;
    const int bn  = blockIdx.x * 128;

    float acc[2][8][4];
    #pragma unroll
    for (int mi = 0; mi < 2; mi++)
        #pragma unroll
        for (int ni = 0; ni < 8; ni++)
            #pragma unroll
            for (int t = 0; t < 4; t++) acc[mi][ni][t] = 0.f;

    gemm_mainloop(sbase, Ahi, Alo, Whi, Wlo, bm, bn, tid, acc);

    const int lane = tid & 31;
    const int w    = tid >> 5;
    const int wm0  = (w & 3) * 32;
    const int wn0  = (w >> 2) * 64;

    #pragma unroll
    for (int mi = 0; mi < 2; mi++) {
        #pragma unroll
        for (int ni = 0; ni < 8; ni++) {
            int row0 = bm + wm0 + mi * 16 + (lane >> 2);
            int col  = bn + wn0 + ni * 8 + (lane & 3) * 2;
            float b0 = bias[col], b1 = bias[col + 1];
            float2 a; a.x = acc[mi][ni][0] + b0; a.y = acc[mi][ni][1] + b1;
            float2 c; c.x = acc[mi][ni][2] + b0; c.y = acc[mi][ni][3] + b1;
            *(float2*)&out[(size_t)row0 * C_ + col]       = a;
            *(float2*)&out[(size_t)(row0 + 8) * C_ + col] = c;
        }
    }
}

// =============================================================================
// Tensor-core flash attention (causal), 3-stage TMA-bulk KV pipeline.
// =============================================================================
constexpr int ARS       = 72;                 // Q smem row stride (bf16)
constexpr int QS_BYTES  = 128 * ARS * 2;      // 18432
constexpr int KV_TILE   = 64 * 64 * 2;        // 8192 bytes per operand tile
constexpr int KV_STAGE  = 4 * KV_TILE;        // 32768 (Khi,Klo,Vhi,Vlo)
constexpr int ATT_SMEM  = 2 * QS_BYTES + 3 * KV_STAGE + 64;

__device__ __forceinline__ void att_issue_kv(
    uint32_t st, uint32_t mbar,
    const __nv_bfloat16* __restrict__ Kh, const __nv_bfloat16* __restrict__ Kl,
    const __nv_bfloat16* __restrict__ Vh, const __nv_bfloat16* __restrict__ Vl,
    int kt)
{
    const int k0 = kt * 64;
    MBARRIER_EXPECT_TX(mbar, KV_STAGE);
    #pragma unroll
    for (int tk = 0; tk < 2; tk++) {
        bulk_g2s(st + 0 * KV_TILE + tk * 4096, Kh + ((size_t)tk * T_ + k0) * 32, 4096, mbar);
        bulk_g2s(st + 1 * KV_TILE + tk * 4096, Kl + ((size_t)tk * T_ + k0) * 32, 4096, mbar);
        bulk_g2s(st + 2 * KV_TILE + tk * 4096, Vh + ((size_t)(2 * kt + tk) * 64) * 32, 4096, mbar);
        bulk_g2s(st + 3 * KV_TILE + tk * 4096, Vl + ((size_t)(2 * kt + tk) * 64) * 32, 4096, mbar);
    }
}

__global__ __launch_bounds__(256, 1) void attn_tc(
    const __nv_bfloat16* __restrict__ qhi, const __nv_bfloat16* __restrict__ qlo,
    const __nv_bfloat16* __restrict__ khi, const __nv_bfloat16* __restrict__ klo,
    const __nv_bfloat16* __restrict__ vthi, const __nv_bfloat16* __restrict__ vtlo,
    __nv_bfloat16* __restrict__ out_hi, __nv_bfloat16* __restrict__ out_lo)
{
    extern __shared__ __align__(1024) char smem[];
    const uint32_t sb  = smem_u32(smem);
    const uint32_t sQh = sb, sQl = sb + QS_BYTES;
    const uint32_t kvb = sb + 2 * QS_BYTES;
    const uint32_t mbB = kvb + 3 * KV_STAGE;
    const int tid  = threadIdx.x;
    const int lane = tid & 31;
    const int w    = tid >> 5;
    const int bh   = blockIdx.x;
    const int qi   = (int)gridDim.y - 1 - (int)blockIdx.y;  // longest first
    const int q0   = qi * 128;
    const int ktmax = 2 * qi + 1;
    const float SC = 0.18033688011112042f;   // hd^-0.5 * log2(e)

    const __nv_bfloat16* Kh = khi  + (size_t)bh * T_ * HD;
    const __nv_bfloat16* Kl = klo  + (size_t)bh * T_ * HD;
    const __nv_bfloat16* Vh = vthi + (size_t)bh * HD * T_;
    const __nv_bfloat16* Vl = vtlo + (size_t)bh * HD * T_;

    // Q prologue loads (plain layout -> ARS smem)
    #pragma unroll
    for (int it = 0; it < 4; it++) {
        int id  = tid + it * 256;
        int row = id >> 3;
        int ch  = id & 7;
        uint32_t so = (uint32_t)(row * (ARS * 2) + ch * 16);
        size_t go = ((size_t)(bh * T_ + q0 + row) * HD + ch * 8) * 2;
        cp_async16(sQh + so, (const char*)qhi + go);
        cp_async16(sQl + so, (const char*)qlo + go);
    }
    CP_ASYNC_COMMIT();

    if (tid == 0) {
        MBARRIER_INIT(mbB + 0, 1);
        MBARRIER_INIT(mbB + 8, 1);
        MBARRIER_INIT(mbB + 16, 1);
    }
    __syncthreads();

    // KV tiles 0 and 1 (ktmax >= 1 always)
    if (tid == 0) {
        att_issue_kv(kvb,            mbB + 0, Kh, Kl, Vh, Vl, 0);
        att_issue_kv(kvb + KV_STAGE, mbB + 8, Kh, Kl, Vh, Vl, 1);
    }

    float o[8][4];
    #pragma unroll
    for (int n = 0; n < 8; n++)
        #pragma unroll
        for (int t = 0; t < 4; t++) o[n][t] = 0.f;
    float m0 = -1e30f, m1 = -1e30f, l0 = 0.f, l1 = 0.f;
    uint32_t qfh[4][4], qfl[4][4];

    const int rlo_base = q0 + w * 16 + (lane >> 2);
    int ph[3] = {0, 0, 0};
    int s = 0;

    for (int kt = 0; kt <= ktmax; kt++) {
        MBARRIER_WAIT_PARITY(mbB + s * 8, ph[s]);
        ph[s] ^= 1;
        if (kt == 0) CP_ASYNC_WAIT(0);
        __syncthreads();   // all warps done with stage (s+2)%3 (iter kt-1); Q ready

        if (kt == 0) {
            #pragma unroll
            for (int kc = 0; kc < 4; kc++) {
                uint32_t off = (uint32_t)((w * 16 + (lane & 15)) * (ARS * 2)
                                          + kc * 32 + ((lane >> 4) << 4));
                ldsm_x4(sQh + off, qfh[kc]);
                ldsm_x4(sQl + off, qfl[kc]);
            }
        }

        if (kt + 2 <= ktmax && tid == 0) {
            int s2 = s - 1; if (s2 < 0) s2 += 3;   // (kt+2)%3
            att_issue_kv(kvb + (uint32_t)s2 * KV_STAGE, mbB + s2 * 8,
                         Kh, Kl, Vh, Vl, kt + 2);
        }

        bool active = (kt * 64 <= q0 + w * 16 + 15);

        if (active) {
            const uint32_t st  = kvb + (uint32_t)s * KV_STAGE;
            const uint32_t sKh = st, sKl = st + KV_TILE;
            const uint32_t sVh = st + 2 * KV_TILE, sVl = st + 3 * KV_TILE;

            float sv[8][4];
            #pragma unroll
            for (int n = 0; n < 8; n++)
                #pragma unroll
                for (int t = 0; t < 4; t++) sv[n][t] = 0.f;

            // S = Q K^T: contraction over hd
            #pragma unroll
            for (int kc = 0; kc < 4; kc++) {
                const int tk = kc >> 1;
                uint32_t kh[8][2], kl[8][2];
                #pragma unroll
                for (int p = 0; p < 4; p++) {
                    int r = p * 16 + (lane & 7) + ((lane >> 4) & 1) * 8;
                    int c = (kc & 1) * 2 + ((lane >> 3) & 1);
                    uint32_t off = (uint32_t)(tk * 4096 + r * 64
                                              + ((c ^ ((r >> 1) & 3)) << 4));
                    uint32_t tmp[4];
                    ldsm_x4(sKh + off, tmp);
                    kh[2 * p][0] = tmp[0]; kh[2 * p][1] = tmp[1];
                    kh[2 * p + 1][0] = tmp[2]; kh[2 * p + 1][1] = tmp[3];
                    ldsm_x4(sKl + off, tmp);
                    kl[2 * p][0] = tmp[0]; kl[2 * p][1] = tmp[1];
                    kl[2 * p + 1][0] = tmp[2]; kl[2 * p + 1][1] = tmp[3];
                }
                #pragma unroll
                for (int n = 0; n < 8; n++) mma_bf16(sv[n], qfh[kc], kh[n]);
                #pragma unroll
                for (int n = 0; n < 8; n++) mma_bf16(sv[n], qfh[kc], kl[n]);
                #pragma unroll
                for (int n = 0; n < 8; n++) mma_bf16(sv[n], qfl[kc], kh[n]);
            }

            const int rlo = rlo_base;
            const int rhi = rlo + 8;
            const bool needmask = (kt * 64 + 63 > q0 + w * 16);
            float mx0 = m0, mx1 = m1;
            #pragma unroll
            for (int n = 0; n < 8; n++) {
                int j = kt * 64 + n * 8 + (lane & 3) * 2;
                sv[n][0] *= SC; sv[n][1] *= SC; sv[n][2] *= SC; sv[n][3] *= SC;
                if (needmask) {
                    if (j     > rlo) sv[n][0] = -1e30f;
                    if (j + 1 > rlo) sv[n][1] = -1e30f;
                    if (j     > rhi) sv[n][2] = -1e30f;
                    if (j + 1 > rhi) sv[n][3] = -1e30f;
                }
                mx0 = fmaxf(mx0, fmaxf(sv[n][0], sv[n][1]));
                mx1 = fmaxf(mx1, fmaxf(sv[n][2], sv[n][3]));
            }
            mx0 = fmaxf(mx0, __shfl_xor_sync(0xffffffffu, mx0, 1));
            mx0 = fmaxf(mx0, __shfl_xor_sync(0xffffffffu, mx0, 2));
            mx1 = fmaxf(mx1, __shfl_xor_sync(0xffffffffu, mx1, 1));
            mx1 = fmaxf(mx1, __shfl_xor_sync(0xffffffffu, mx1, 2));
            const float a0 = ex2f(m0 - mx0);
            const float a1 = ex2f(m1 - mx1);
            m0 = mx0; m1 = mx1;

            float sum0 = 0.f, sum1 = 0.f;
            #pragma unroll
            for (int n = 0; n < 8; n++) {
                sv[n][0] = ex2f(sv[n][0] - mx0);
                sv[n][1] = ex2f(sv[n][1] - mx0);
                sv[n][2] = ex2f(sv[n][2] - mx1);
                sv[n][3] = ex2f(sv[n][3] - mx1);
                sum0 += sv[n][0] + sv[n][1];
                sum1 += sv[n][2] + sv[n][3];
            }
            l0 = l0 * a0 + sum0;
            l1 = l1 * a1 + sum1;
            #pragma unroll
            for (int n = 0; n < 8; n++) {
                o[n][0] *= a0; o[n][1] *= a0; o[n][2] *= a1; o[n][3] *= a1;
            }

            uint32_t ph_[4][4], pl_[4][4];
            #pragma unroll
            for (int kc = 0; kc < 4; kc++) {
                psplit(sv[2 * kc][0],     sv[2 * kc][1],     ph_[kc][0], pl_[kc][0]);
                psplit(sv[2 * kc][2],     sv[2 * kc][3],     ph_[kc][1], pl_[kc][1]);
                psplit(sv[2 * kc + 1][0], sv[2 * kc + 1][1], ph_[kc][2], pl_[kc][2]);
                psplit(sv[2 * kc + 1][2], sv[2 * kc + 1][3], ph_[kc][3], pl_[kc][3]);
            }

            // O += P V
            #pragma unroll
            for (int kc = 0; kc < 4; kc++) {
                const int tk = kc >> 1;
                uint32_t vh[8][2], vl[8][2];
                #pragma unroll
                for (int p = 0; p < 4; p++) {
                    int r = p * 16 + (lane & 7) + ((lane >> 4) & 1) * 8;
                    int c = (kc & 1) * 2 + ((lane >> 3) & 1);
                    uint32_t off = (uint32_t)(tk * 4096 + r * 64
                                              + ((c ^ ((r >> 1) & 3)) << 4));
                    uint32_t tmp[4];
                    ldsm_x4(sVh + off, tmp);
                    vh[2 * p][0] = tmp[0]; vh[2 * p][1] = tmp[1];
                    vh[2 * p + 1][0] = tmp[2]; vh[2 * p + 1][1] = tmp[3];
                    ldsm_x4(sVl + off, tmp);
                    vl[2 * p][0] = tmp[0]; vl[2 * p][1] = tmp[1];
                    vl[2 * p + 1][0] = tmp[2]; vl[2 * p + 1][1] = tmp[3];
                }
                #pragma unroll
                for (int n = 0; n < 8; n++) mma_bf16(o[n], ph_[kc], vh[n]);
                #pragma unroll
                for (int n = 0; n < 8; n++) mma_bf16(o[n], ph_[kc], vl[n]);
                #pragma unroll
                for (int n = 0; n < 8; n++) mma_bf16(o[n], pl_[kc], vh[n]);
            }
        }
        s = (s == 2) ? 0 : s + 1;
    }

    l0 += __shfl_xor_sync(0xffffffffu, l0, 1);
    l0 += __shfl_xor_sync(0xffffffffu, l0, 2);
    l1 += __shfl_xor_sync(0xffffffffu, l1, 1);
    l1 += __shfl_xor_sync(0xffffffffu, l1, 2);
    const float inv0 = 1.f / l0;
    const float inv1 = 1.f / l1;

    // epilogue: split-store into TILED GEMM layout (rows = b*T+t, cols = h*64+d)
    const int b = bh >> 4, h = bh & 15;
    const int r0 = b * T_ + q0 + w * 16 + (lane >> 2);
    const int r1 = r0 + 8;
    #pragma unroll
    for (int n = 0; n < 8; n++) {
        int cglob = h * HD + n * 8 + (lane & 3) * 2;
        uint32_t hh, ll;
        size_t o0 = tiled_off(8192, r0, cglob);
        psplit(o[n][0] * inv0, o[n][1] * inv0, hh, ll);
        *(uint32_t*)(out_hi + o0) = hh;
        *(uint32_t*)(out_lo + o0) = ll;
        size_t o1 = tiled_off(8192, r1, cglob);
        psplit(o[n][2] * inv1, o[n][3] * inv1, hh, ll);
        *(uint32_t*)(out_hi + o1) = hh;
        *(uint32_t*)(out_lo + o1) = ll;
    }
}

// =============================================================================
extern "C" void kernel_launch(void* const* d_in, const int* in_sizes, int n_in,
                              void* d_out, int out_size)
{
    (void)in_sizes; (void)n_in; (void)out_size;
    const float* x  = (const float*)d_in[0];
    const float* wq = (const float*)d_in[1];
    const float* bq = (const float*)d_in[2];
    const float* wk = (const float*)d_in[3];
    const float* bk = (const float*)d_in[4];
    const float* wv = (const float*)d_in[5];
    const float* bv = (const float*)d_in[6];
    const float* wo = (const float*)d_in[7];
    const float* bo = (const float*)d_in[8];
    float* out = (float*)d_out;

    __nv_bfloat16 *ahi, *alo, *whi, *wlo;
    __nv_bfloat16 *qhi, *qlo, *khi, *klo, *vthi, *vtlo;
    cudaGetSymbolAddress((void**)&ahi,  g_ahi);
    cudaGetSymbolAddress((void**)&alo,  g_alo);
    cudaGetSymbolAddress((void**)&whi,  g_whi);
    cudaGetSymbolAddress((void**)&wlo,  g_wlo);
    cudaGetSymbolAddress((void**)&qhi,  g_qhi);
    cudaGetSymbolAddress((void**)&qlo,  g_qlo);
    cudaGetSymbolAddress((void**)&khi,  g_khi);
    cudaGetSymbolAddress((void**)&klo,  g_klo);
    cudaGetSymbolAddress((void**)&vthi, g_vthi);
    cudaGetSymbolAddress((void**)&vtlo, g_vtlo);

    const int nW = C_ * C_;

    split_all<<<12288, 256>>>(x, wq, wk, wv, wo, ahi, alo, whi, wlo);

    cudaFuncSetAttribute(gemm_qkv, cudaFuncAttributeMaxDynamicSharedMemorySize, GEMM_SMEM);
    cudaFuncSetAttribute(gemm_out, cudaFuncAttributeMaxDynamicSharedMemorySize, GEMM_SMEM);
    cudaFuncSetAttribute(attn_tc,  cudaFuncAttributeMaxDynamicSharedMemorySize, ATT_SMEM);

    gemm_qkv<<<dim3(C_ / 128, M_ / 128, 3), 256, GEMM_SMEM>>>(
        ahi, alo, whi, wlo, bq, bk, bv, qhi, qlo, khi, klo, vthi, vtlo);

    attn_tc<<<dim3(B_ * H_, T_ / 128), 256, ATT_SMEM>>>(qhi, qlo, khi, klo,
                                                        vthi, vtlo, ahi, alo);

    gemm_out<<<dim3(C_ / 128, M_ / 128), 256, GEMM_SMEM>>>(
        ahi, alo, whi + 3 * nW, wlo + 3 * nW, bo, out);
}

// round 14
// speedup vs baseline: 1.0267x; 1.0267x over previous
#include <cuda_runtime.h>
#include <cuda_bf16.h>
#include <math.h>
#include <stdint.h>

// Problem constants
constexpr int B_  = 4;
constexpr int T_  = 2048;
constexpr int C_  = 1024;
constexpr int H_  = 16;
constexpr int HD  = 64;
constexpr int M_  = B_ * T_;

// -------------------- scratch (static device allocations) --------------------
// GEMM operands + K + V^T all use the K-CHUNK-TILED, PRE-SWIZZLED layout:
//   element (row, k) -> ((k/32)*NROWS + row)*32 + (((k>>3)&3) ^ ((row>>1)&3))*8 + (k&7)
__device__ __nv_bfloat16 g_ahi[M_ * C_];     // activations (x, later attn-out)
__device__ __nv_bfloat16 g_alo[M_ * C_];
__device__ __nv_bfloat16 g_whi[4 * C_ * C_]; // weights (q,k,v,o)
__device__ __nv_bfloat16 g_wlo[4 * C_ * C_];
__device__ __nv_bfloat16 g_qhi[B_ * H_ * T_ * HD];  // [B,H,T,hd] plain
__device__ __nv_bfloat16 g_qlo[B_ * H_ * T_ * HD];
__device__ __nv_bfloat16 g_khi[B_ * H_ * T_ * HD];  // per-bh tiled: rows=T, k=hd
__device__ __nv_bfloat16 g_klo[B_ * H_ * T_ * HD];
__device__ __nv_bfloat16 g_vthi[B_ * H_ * HD * T_]; // per-bh tiled: rows=hd, k=T
__device__ __nv_bfloat16 g_vtlo[B_ * H_ * HD * T_];

// =============================================================================
// helpers (compute_103-portable)
// =============================================================================
__device__ __forceinline__ uint32_t smem_u32(const void* p) {
    uint32_t a;
    asm("{ .reg .u64 t; cvta.to.shared.u64 t, %1; cvt.u32.u64 %0, t; }"
        : "=r"(a) : "l"(p));
    return a;
}
__device__ __forceinline__ void ldsm_x4(uint32_t addr, uint32_t* r) {
    asm volatile("ldmatrix.sync.aligned.m8n8.x4.shared.b16 {%0,%1,%2,%3}, [%4];"
                 : "=r"(r[0]), "=r"(r[1]), "=r"(r[2]), "=r"(r[3]) : "r"(addr));
}
__device__ __forceinline__ void mma_bf16(float* d, const uint32_t* a, const uint32_t* b) {
    asm volatile(
        "mma.sync.aligned.m16n8k16.row.col.f32.bf16.bf16.f32 "
        "{%0,%1,%2,%3}, {%4,%5,%6,%7}, {%8,%9}, {%0,%1,%2,%3};"
        : "+f"(d[0]), "+f"(d[1]), "+f"(d[2]), "+f"(d[3])
        : "r"(a[0]), "r"(a[1]), "r"(a[2]), "r"(a[3]), "r"(b[0]), "r"(b[1]));
}
__device__ __forceinline__ void cp_async16(uint32_t dst, const void* src) {
    asm volatile("cp.async.cg.shared.global [%0], [%1], 16;" :: "r"(dst), "l"(src));
}
#define CP_ASYNC_COMMIT() asm volatile("cp.async.commit_group;" ::: "memory")
#define CP_ASYNC_WAIT(n)  asm volatile("cp.async.wait_group %0;" :: "n"(n) : "memory")

// TMA 1D bulk copy global->shared with mbarrier completion
__device__ __forceinline__ void bulk_g2s(uint32_t dst, const void* src,
                                         uint32_t bytes, uint32_t mbar) {
    asm volatile(
        "cp.async.bulk.shared::cluster.global.mbarrier::complete_tx::bytes "
        "[%0], [%1], %2, [%3];"
        :: "r"(dst), "l"(src), "r"(bytes), "r"(mbar) : "memory");
}
#define MBARRIER_INIT(mbar, count) \
    asm volatile("mbarrier.init.shared.b64 [%0], %1;" \
                 :: "r"((uint32_t)(mbar)), "r"((uint32_t)(count)) : "memory")
#define MBARRIER_EXPECT_TX(mbar, bytes) \
    asm volatile("mbarrier.arrive.expect_tx.shared.b64 _, [%0], %1;" \
                 :: "r"((uint32_t)(mbar)), "r"((uint32_t)(bytes)) : "memory")
#define MBARRIER_ARRIVE(mbar) \
    asm volatile("mbarrier.arrive.release.cta.shared::cta.b64 _, [%0];" \
                 :: "r"((uint32_t)(mbar)) : "memory")
#define MBARRIER_WAIT_PARITY(mbar_addr, phase_parity) do { \
    uint32_t _mbar = (uint32_t)(mbar_addr); \
    uint32_t _parity = (uint32_t)(phase_parity); \
    uint32_t _done; \
    asm volatile( \
        "{\n\t.reg .pred p;\n\t" \
        "mbarrier.try_wait.parity.acquire.cta.shared::cta.b64 p, [%1], %2;\n\t" \
        "selp.b32 %0, 1, 0, p;\n\t}" \
        : "=r"(_done) : "r"(_mbar), "r"(_parity) : "memory"); \
    if (!_done) { \
        asm volatile( \
            "{\n\t.reg .pred P1;\n\t" \
            "WAIT_LOOP_%=:\n\t" \
            "mbarrier.try_wait.parity.acquire.cta.shared::cta.b64 P1, [%0], %1, 0x989680;\n\t" \
            "@P1 bra.uni WAIT_DONE_%=;\n\t" \
            "bra.uni WAIT_LOOP_%=;\n\t" \
            "WAIT_DONE_%=:\n\t}" \
            :: "r"(_mbar), "r"(_parity) : "memory"); \
    } \
} while (0)

__device__ __forceinline__ float ex2f(float x) {
    float y;
    asm("ex2.approx.ftz.f32 %0, %1;" : "=f"(y) : "f"(x));
    return y;
}
// pack (x,y) -> bf16x2 hi + bf16x2 lo residual
__device__ __forceinline__ void psplit(float x, float y, uint32_t& hi, uint32_t& lo) {
    __nv_bfloat162 h = __floats2bfloat162_rn(x, y);
    float rx = x - __bfloat162float(h.x);
    float ry = y - __bfloat162float(h.y);
    __nv_bfloat162 l = __floats2bfloat162_rn(rx, ry);
    hi = *(uint32_t*)&h;
    lo = *(uint32_t*)&l;
}

// tiled-layout element offset
__device__ __forceinline__ size_t tiled_off(int nrows, int row, int k) {
    int tk = k >> 5;
    int c  = (k >> 3) & 3;
    int cs = c ^ ((row >> 1) & 3);
    return ((size_t)(tk * nrows + row)) * 32 + cs * 8 + (k & 7);
}

// =============================================================================
// fused split: fp32 -> bf16 hi+lo, written into the tiled GEMM layout.
// =============================================================================
__global__ __launch_bounds__(256) void split_all(
    const float* __restrict__ x,
    const float* __restrict__ wq, const float* __restrict__ wk,
    const float* __restrict__ wv, const float* __restrict__ wo,
    __nv_bfloat16* __restrict__ ahi, __nv_bfloat16* __restrict__ alo,
    __nv_bfloat16* __restrict__ whi, __nv_bfloat16* __restrict__ wlo)
{
    const int nW = C_ * C_;
    int blk = blockIdx.x;
    const float* src;
    __nv_bfloat16 *hi, *lo;
    int base, nrows;
    if (blk < 8192) {
        src = x; hi = ahi; lo = alo; base = blk; nrows = 8192;
    } else {
        int r = blk - 8192;
        int ws = r >> 10;
        base = r & 1023;
        src = (ws == 0) ? wq : (ws == 1) ? wk : (ws == 2) ? wv : wo;
        hi = whi + (size_t)ws * nW;
        lo = wlo + (size_t)ws * nW;
        nrows = 1024;
    }
    int i = (base * 256 + threadIdx.x) * 4;
    int row = i >> 10;
    int k   = i & 1023;
    float4 v = *(const float4*)(src + i);
    uint32_t h0, l0, h1, l1;
    psplit(v.x, v.y, h0, l0);
    psplit(v.z, v.w, h1, l1);
    size_t off = tiled_off(nrows, row, k);
    *(uint32_t*)(hi + off)     = h0;
    *(uint32_t*)(hi + off + 2) = h1;
    *(uint32_t*)(lo + off)     = l0;
    *(uint32_t*)(lo + off + 2) = l1;
}

// =============================================================================
// GEMM mainloop: 2-stage TMA bulk pipeline with PRODUCER/CONSUMER mbarriers.
// No __syncthreads in the mainloop: consumers wait full[s] (acquire), each
// warp release-arrives on empty[s] (count=8) after its reads; only tid 0
// waits empty before reusing a stage. Warp skew is absorbed, not serialized.
// =============================================================================
constexpr int TILE_B      = 128 * 64;                // 8192 bytes per operand tile
constexpr int STAGE_BYTES = 4 * TILE_B;              // 32768
constexpr int GEMM_SMEM   = 2 * STAGE_BYTES + 64;    // + mbarriers

__device__ __forceinline__ void gemm_issue_stage(
    uint32_t st, uint32_t mbar,
    const __nv_bfloat16* __restrict__ Ahi, const __nv_bfloat16* __restrict__ Alo,
    const __nv_bfloat16* __restrict__ Whi, const __nv_bfloat16* __restrict__ Wlo,
    int bm, int bn, int tk)
{
    MBARRIER_EXPECT_TX(mbar, STAGE_BYTES);
    bulk_g2s(st,              Ahi + (size_t)(tk * 8192 + bm) * 32, TILE_B, mbar);
    bulk_g2s(st + TILE_B,     Alo + (size_t)(tk * 8192 + bm) * 32, TILE_B, mbar);
    bulk_g2s(st + 2 * TILE_B, Whi + (size_t)(tk * 1024 + bn) * 32, TILE_B, mbar);
    bulk_g2s(st + 3 * TILE_B, Wlo + (size_t)(tk * 1024 + bn) * 32, TILE_B, mbar);
}

__device__ __forceinline__ void gemm_mainloop(
    uint32_t sbase,
    const __nv_bfloat16* __restrict__ Ahi, const __nv_bfloat16* __restrict__ Alo,
    const __nv_bfloat16* __restrict__ Whi, const __nv_bfloat16* __restrict__ Wlo,
    int bm, int bn, int tid, float acc[2][8][4])
{
    const int lane = tid & 31;
    const int w    = tid >> 5;
    const int wm0  = (w & 3) * 32;
    const int wn0  = (w >> 2) * 64;
    constexpr int NC = C_ / 32;

    const uint32_t mbF0 = sbase + 2 * STAGE_BYTES;       // full stage 0
    const uint32_t mbF1 = mbF0 + 8;                      // full stage 1
    const uint32_t mbE0 = mbF0 + 16;                     // empty stage 0 (count 8)
    const uint32_t mbE1 = mbF0 + 24;                     // empty stage 1

    if (tid == 0) {
        MBARRIER_INIT(mbF0, 1); MBARRIER_INIT(mbF1, 1);
        MBARRIER_INIT(mbE0, 8); MBARRIER_INIT(mbE1, 8);
    }
    __syncthreads();

    // prologue: chunks 0, 1 into stages 0, 1 (stages fresh — no empty wait)
    if (tid == 0) {
        gemm_issue_stage(sbase,               mbF0, Ahi, Alo, Whi, Wlo, bm, bn, 0);
        gemm_issue_stage(sbase + STAGE_BYTES, mbF1, Ahi, Alo, Whi, Wlo, bm, bn, 1);
    }

    int phF0 = 0, phF1 = 0, phE0 = 0, phE1 = 0;

    for (int ck = 0; ck < NC; ck++) {
        const int s = ck & 1;

        // producer: reuse stage s^1 for chunk ck+1... already holds ck+1.
        // Issue chunk ck+1 into stage s^1 was done at iter ck-1 (or prologue).
        // Here: once consumers emptied stage s^1 (chunk ck-1), issue chunk ck+1?
        // Indexing: at top of iter ck (ck>=1), stage s^1 finished chunk ck-1 at
        // end of iter ck-1; issue chunk ck+1 into it now.
        if (tid == 0 && ck >= 1 && ck + 1 < NC) {
            if (s == 0) { MBARRIER_WAIT_PARITY(mbE1, phE1); phE1 ^= 1; }
            else        { MBARRIER_WAIT_PARITY(mbE0, phE0); phE0 ^= 1; }
            const uint32_t st   = sbase + (uint32_t)(s ^ 1) * STAGE_BYTES;
            const uint32_t mbar = (s == 0) ? mbF1 : mbF0;
            gemm_issue_stage(st, mbar, Ahi, Alo, Whi, Wlo, bm, bn, ck + 1);
        }

        // consumer: wait data for stage s (per-thread acquire; no CTA rendezvous)
        if (s == 0) { MBARRIER_WAIT_PARITY(mbF0, phF0); phF0 ^= 1; }
        else        { MBARRIER_WAIT_PARITY(mbF1, phF1); phF1 ^= 1; }

        const uint32_t st  = sbase + (uint32_t)s * STAGE_BYTES;
        const uint32_t sAh = st;
        const uint32_t sAl = st + TILE_B;
        const uint32_t sWh = st + 2 * TILE_B;
        const uint32_t sWl = st + 3 * TILE_B;

        #pragma unroll
        for (int kk = 0; kk < 2; kk++) {
            uint32_t ah[2][4], al[2][4];
            #pragma unroll
            for (int mi = 0; mi < 2; mi++) {
                int r = wm0 + mi * 16 + (lane & 15);
                int c = kk * 2 + (lane >> 4);
                uint32_t off = (uint32_t)(r * 64 + ((c ^ ((r >> 1) & 3)) << 4));
                ldsm_x4(sAh + off, ah[mi]);
                ldsm_x4(sAl + off, al[mi]);
            }
            #pragma unroll
            for (int p = 0; p < 4; p++) {
                int r = wn0 + p * 16 + (lane & 7) + ((lane >> 4) & 1) * 8;
                int c = kk * 2 + ((lane >> 3) & 1);
                uint32_t off = (uint32_t)(r * 64 + ((c ^ ((r >> 1) & 3)) << 4));
                uint32_t wh[4], wl[4];
                ldsm_x4(sWh + off, wh);
                ldsm_x4(sWl + off, wl);
                #pragma unroll
                for (int mi = 0; mi < 2; mi++) {
                    mma_bf16(acc[mi][2 * p],     ah[mi], wh + 0);
                    mma_bf16(acc[mi][2 * p + 1], ah[mi], wh + 2);
                    mma_bf16(acc[mi][2 * p],     ah[mi], wl + 0);
                    mma_bf16(acc[mi][2 * p + 1], ah[mi], wl + 2);
                    mma_bf16(acc[mi][2 * p],     al[mi], wh + 0);
                    mma_bf16(acc[mi][2 * p + 1], al[mi], wh + 2);
                }
            }
        }

        // this warp is done reading stage s (ldsm results consumed by the MMAs)
        if (lane == 0) {
            if (s == 0) MBARRIER_ARRIVE(mbE0);
            else        MBARRIER_ARRIVE(mbE1);
        }
    }
    // no trailing sync needed: epilogue touches registers + global only
}

// ---------- fused QKV projection: z selects {q,k,v} ----------
__global__ __launch_bounds__(256, 2) void gemm_qkv(
    const __nv_bfloat16* __restrict__ Ahi, const __nv_bfloat16* __restrict__ Alo,
    const __nv_bfloat16* __restrict__ Wh,  const __nv_bfloat16* __restrict__ Wl,
    const float* __restrict__ b0, const float* __restrict__ b1,
    const float* __restrict__ b2,
    __nv_bfloat16* __restrict__ qh, __nv_bfloat16* __restrict__ ql,
    __nv_bfloat16* __restrict__ kh, __nv_bfloat16* __restrict__ kl,
    __nv_bfloat16* __restrict__ vh, __nv_bfloat16* __restrict__ vl)
{
    extern __shared__ __align__(1024) char smem[];
    const uint32_t sbase = smem_u32(smem);
    const int tid = threadIdx.x;
    const int bm  = blockIdx.y * 128;
    const int bn  = blockIdx.x * 128;
    const int z   = blockIdx.z;
    const int nW  = C_ * C_;

    const float* bias = (z == 0) ? b0 : (z == 1) ? b1 : b2;

    float acc[2][8][4];
    #pragma unroll
    for (int mi = 0; mi < 2; mi++)
        #pragma unroll
        for (int ni = 0; ni < 8; ni++)
            #pragma unroll
            for (int t = 0; t < 4; t++) acc[mi][ni][t] = 0.f;

    gemm_mainloop(sbase, Ahi, Alo, Wh + (size_t)z * nW, Wl + (size_t)z * nW,
                  bm, bn, tid, acc);

    const int lane = tid & 31;
    const int w    = tid >> 5;
    const int wm0  = (w & 3) * 32;
    const int wn0  = (w >> 2) * 64;

    #pragma unroll
    for (int mi = 0; mi < 2; mi++) {
        #pragma unroll
        for (int ni = 0; ni < 8; ni++) {
            int row0 = bm + wm0 + mi * 16 + (lane >> 2);
            int col  = bn + wn0 + ni * 8 + (lane & 3) * 2;
            float bb0 = bias[col], bb1 = bias[col + 1];
            float v00 = acc[mi][ni][0] + bb0, v01 = acc[mi][ni][1] + bb1;
            float v10 = acc[mi][ni][2] + bb0, v11 = acc[mi][ni][3] + bb1;
            int h = col >> 6, d = col & 63;
            if (z == 0) {   // Q plain [B,H,T,hd]
                uint32_t hh, ll;
                {
                    int b = row0 >> 11, t = row0 & 2047;
                    size_t o = ((size_t)((b * H_ + h) * T_ + t)) * HD + d;
                    psplit(v00, v01, hh, ll);
                    *(uint32_t*)(qh + o) = hh; *(uint32_t*)(ql + o) = ll;
                }
                {
                    int r1 = row0 + 8;
                    int b = r1 >> 11, t = r1 & 2047;
                    size_t o = ((size_t)((b * H_ + h) * T_ + t)) * HD + d;
                    psplit(v10, v11, hh, ll);
                    *(uint32_t*)(qh + o) = hh; *(uint32_t*)(ql + o) = ll;
                }
            } else if (z == 1) {   // K tiled per bh: rows=T, k=hd
                uint32_t hh, ll;
                {
                    int b = row0 >> 11, t = row0 & 2047;
                    size_t o = (size_t)(b * H_ + h) * T_ * HD + tiled_off(T_, t, d);
                    psplit(v00, v01, hh, ll);
                    *(uint32_t*)(kh + o) = hh; *(uint32_t*)(kl + o) = ll;
                }
                {
                    int r1 = row0 + 8;
                    int b = r1 >> 11, t = r1 & 2047;
                    size_t o = (size_t)(b * H_ + h) * T_ * HD + tiled_off(T_, t, d);
                    psplit(v10, v11, hh, ll);
                    *(uint32_t*)(kh + o) = hh; *(uint32_t*)(kl + o) = ll;
                }
            } else {       // V^T tiled per bh: rows=hd, k=T
                int b = row0 >> 11, t = row0 & 2047;
                size_t bb = (size_t)(b * H_ + h) * HD * T_;
                __nv_bfloat16 h00 = __float2bfloat16_rn(v00);
                __nv_bfloat16 h01 = __float2bfloat16_rn(v01);
                __nv_bfloat16 h10 = __float2bfloat16_rn(v10);
                __nv_bfloat16 h11 = __float2bfloat16_rn(v11);
                size_t o00 = bb + tiled_off(HD, d,     t);
                size_t o01 = bb + tiled_off(HD, d + 1, t);
                size_t o10 = bb + tiled_off(HD, d,     t + 8);
                size_t o11 = bb + tiled_off(HD, d + 1, t + 8);
                vh[o00] = h00; vh[o01] = h01; vh[o10] = h10; vh[o11] = h11;
                vl[o00] = __float2bfloat16_rn(v00 - __bfloat162float(h00));
                vl[o01] = __float2bfloat16_rn(v01 - __bfloat162float(h01));
                vl[o10] = __float2bfloat16_rn(v10 - __bfloat162float(h10));
                vl[o11] = __float2bfloat16_rn(v11 - __bfloat162float(h11));
            }
        }
    }
}

// ---------- O-projection: fp32 row-major output ----------
__global__ __launch_bounds__(256, 2) void gemm_out(
    const __nv_bfloat16* __restrict__ Ahi, const __nv_bfloat16* __restrict__ Alo,
    const __nv_bfloat16* __restrict__ Whi, const __nv_bfloat16* __restrict__ Wlo,
    const float* __restrict__ bias, float* __restrict__ out)
{
    extern __shared__ __align__(1024) char smem[];
    const uint32_t sbase = smem_u32(smem);
    const int tid = threadIdx.x;
    const int bm  = blockIdx.y * 128;
    const int bn  = blockIdx.x * 128;

    float acc[2][8][4];
    #pragma unroll
    for (int mi = 0; mi < 2; mi++)
        #pragma unroll
        for (int ni = 0; ni < 8; ni++)
            #pragma unroll
            for (int t = 0; t < 4; t++) acc[mi][ni][t] = 0.f;

    gemm_mainloop(sbase, Ahi, Alo, Whi, Wlo, bm, bn, tid, acc);

    const int lane = tid & 31;
    const int w    = tid >> 5;
    const int wm0  = (w & 3) * 32;
    const int wn0  = (w >> 2) * 64;

    #pragma unroll
    for (int mi = 0; mi < 2; mi++) {
        #pragma unroll
        for (int ni = 0; ni < 8; ni++) {
            int row0 = bm + wm0 + mi * 16 + (lane >> 2);
            int col  = bn + wn0 + ni * 8 + (lane & 3) * 2;
            float b0 = bias[col], b1 = bias[col + 1];
            float2 a; a.x = acc[mi][ni][0] + b0; a.y = acc[mi][ni][1] + b1;
            float2 c; c.x = acc[mi][ni][2] + b0; c.y = acc[mi][ni][3] + b1;
            *(float2*)&out[(size_t)row0 * C_ + col]       = a;
            *(float2*)&out[(size_t)(row0 + 8) * C_ + col] = c;
        }
    }
}

// =============================================================================
// Tensor-core flash attention (causal), 2-stage TMA-bulk KV pipeline
// (round-12 exact — known good at 728.8us config).
// =============================================================================
constexpr int ARS       = 72;                 // Q smem row stride (bf16)
constexpr int QS_BYTES  = 128 * ARS * 2;      // 18432
constexpr int KV_TILE   = 64 * 64 * 2;        // 8192 bytes per operand tile
constexpr int KV_STAGE  = 4 * KV_TILE;        // 32768 (Khi,Klo,Vhi,Vlo)
constexpr int ATT_SMEM  = 2 * QS_BYTES + 2 * KV_STAGE + 64;

__global__ __launch_bounds__(256, 1) void attn_tc(
    const __nv_bfloat16* __restrict__ qhi, const __nv_bfloat16* __restrict__ qlo,
    const __nv_bfloat16* __restrict__ khi, const __nv_bfloat16* __restrict__ klo,
    const __nv_bfloat16* __restrict__ vthi, const __nv_bfloat16* __restrict__ vtlo,
    __nv_bfloat16* __restrict__ out_hi, __nv_bfloat16* __restrict__ out_lo)
{
    extern __shared__ __align__(1024) char smem[];
    const uint32_t sb  = smem_u32(smem);
    const uint32_t sQh = sb, sQl = sb + QS_BYTES;
    const uint32_t kvb = sb + 2 * QS_BYTES;
    const uint32_t mbar0 = kvb + 2 * KV_STAGE;
    const uint32_t mbar1 = mbar0 + 8;
    const int tid  = threadIdx.x;
    const int lane = tid & 31;
    const int w    = tid >> 5;
    const int bh   = blockIdx.x;
    const int qi   = (int)gridDim.y - 1 - (int)blockIdx.y;  // longest first
    const int q0   = qi * 128;
    const int ktmax = 2 * qi + 1;
    const float SC = 0.18033688011112042f;   // hd^-0.5 * log2(e)

    const __nv_bfloat16* Kh = khi  + (size_t)bh * T_ * HD;
    const __nv_bfloat16* Kl = klo  + (size_t)bh * T_ * HD;
    const __nv_bfloat16* Vh = vthi + (size_t)bh * HD * T_;
    const __nv_bfloat16* Vl = vtlo + (size_t)bh * HD * T_;

    // Q prologue loads (plain layout -> ARS smem)
    #pragma unroll
    for (int it = 0; it < 4; it++) {
        int id  = tid + it * 256;
        int row = id >> 3;
        int ch  = id & 7;
        uint32_t so = (uint32_t)(row * (ARS * 2) + ch * 16);
        size_t go = ((size_t)(bh * T_ + q0 + row) * HD + ch * 8) * 2;
        cp_async16(sQh + so, (const char*)qhi + go);
        cp_async16(sQl + so, (const char*)qlo + go);
    }
    CP_ASYNC_COMMIT();

    if (tid == 0) { MBARRIER_INIT(mbar0, 1); MBARRIER_INIT(mbar1, 1); }
    __syncthreads();

    // KV tile 0 via TMA bulk
    if (tid == 0) {
        MBARRIER_EXPECT_TX(mbar0, KV_STAGE);
        #pragma unroll
        for (int tk = 0; tk < 2; tk++) {
            bulk_g2s(kvb + 0 * KV_TILE + tk * 4096, Kh + ((size_t)tk * T_) * 32, 4096, mbar0);
            bulk_g2s(kvb + 1 * KV_TILE + tk * 4096, Kl + ((size_t)tk * T_) * 32, 4096, mbar0);
            bulk_g2s(kvb + 2 * KV_TILE + tk * 4096, Vh + ((size_t)tk * 64) * 32, 4096, mbar0);
            bulk_g2s(kvb + 3 * KV_TILE + tk * 4096, Vl + ((size_t)tk * 64) * 32, 4096, mbar0);
        }
    }

    float o[8][4];
    #pragma unroll
    for (int n = 0; n < 8; n++)
        #pragma unroll
        for (int t = 0; t < 4; t++) o[n][t] = 0.f;
    float m0 = -1e30f, m1 = -1e30f, l0 = 0.f, l1 = 0.f;
    uint32_t qfh[4][4], qfl[4][4];

    const int rlo_base = q0 + w * 16 + (lane >> 2);
    int ph0 = 0, ph1 = 0;

    for (int kt = 0; kt <= ktmax; kt++) {
        const int s = kt & 1;
        if (s == 0) { MBARRIER_WAIT_PARITY(mbar0, ph0); ph0 ^= 1; }
        else        { MBARRIER_WAIT_PARITY(mbar1, ph1); ph1 ^= 1; }
        if (kt == 0) CP_ASYNC_WAIT(0);
        __syncthreads();   // all threads done with stage s^1 (iter kt-1); Q ready

        if (kt == 0) {
            #pragma unroll
            for (int kc = 0; kc < 4; kc++) {
                uint32_t off = (uint32_t)((w * 16 + (lane & 15)) * (ARS * 2)
                                          + kc * 32 + ((lane >> 4) << 4));
                ldsm_x4(sQh + off, qfh[kc]);
                ldsm_x4(sQl + off, qfl[kc]);
            }
        }

        if (kt + 1 <= ktmax && tid == 0) {
            const uint32_t st   = kvb + (uint32_t)(s ^ 1) * KV_STAGE;
            const uint32_t mbar = (s == 0) ? mbar1 : mbar0;
            const int k0 = (kt + 1) * 64;
            MBARRIER_EXPECT_TX(mbar, KV_STAGE);
            #pragma unroll
            for (int tk = 0; tk < 2; tk++) {
                bulk_g2s(st + 0 * KV_TILE + tk * 4096,
                         Kh + ((size_t)tk * T_ + k0) * 32, 4096, mbar);
                bulk_g2s(st + 1 * KV_TILE + tk * 4096,
                         Kl + ((size_t)tk * T_ + k0) * 32, 4096, mbar);
                bulk_g2s(st + 2 * KV_TILE + tk * 4096,
                         Vh + ((size_t)(2 * (kt + 1) + tk) * 64) * 32, 4096, mbar);
                bulk_g2s(st + 3 * KV_TILE + tk * 4096,
                         Vl + ((size_t)(2 * (kt + 1) + tk) * 64) * 32, 4096, mbar);
            }
        }

        bool active = (kt * 64 <= q0 + w * 16 + 15);

        if (active) {
            const uint32_t st  = kvb + (uint32_t)s * KV_STAGE;
            const uint32_t sKh = st, sKl = st + KV_TILE;
            const uint32_t sVh = st + 2 * KV_TILE, sVl = st + 3 * KV_TILE;

            float sv[8][4];
            #pragma unroll
            for (int n = 0; n < 8; n++)
                #pragma unroll
                for (int t = 0; t < 4; t++) sv[n][t] = 0.f;

            // S = Q K^T: contraction over hd
            #pragma unroll
            for (int kc = 0; kc < 4; kc++) {
                const int tk = kc >> 1;
                uint32_t kh[8][2], kl[8][2];
                #pragma unroll
                for (int p = 0; p < 4; p++) {
                    int r = p * 16 + (lane & 7) + ((lane >> 4) & 1) * 8;
                    int c = (kc & 1) * 2 + ((lane >> 3) & 1);
                    uint32_t off = (uint32_t)(tk * 4096 + r * 64
                                              + ((c ^ ((r >> 1) & 3)) << 4));
                    uint32_t tmp[4];
                    ldsm_x4(sKh + off, tmp);
                    kh[2 * p][0] = tmp[0]; kh[2 * p][1] = tmp[1];
                    kh[2 * p + 1][0] = tmp[2]; kh[2 * p + 1][1] = tmp[3];
                    ldsm_x4(sKl + off, tmp);
                    kl[2 * p][0] = tmp[0]; kl[2 * p][1] = tmp[1];
                    kl[2 * p + 1][0] = tmp[2]; kl[2 * p + 1][1] = tmp[3];
                }
                #pragma unroll
                for (int n = 0; n < 8; n++) mma_bf16(sv[n], qfh[kc], kh[n]);
                #pragma unroll
                for (int n = 0; n < 8; n++) mma_bf16(sv[n], qfh[kc], kl[n]);
                #pragma unroll
                for (int n = 0; n < 8; n++) mma_bf16(sv[n], qfl[kc], kh[n]);
            }

            const int rlo = rlo_base;
            const int rhi = rlo + 8;
            const bool needmask = (kt * 64 + 63 > q0 + w * 16);
            float mx0 = m0, mx1 = m1;
            #pragma unroll
            for (int n = 0; n < 8; n++) {
                int j = kt * 64 + n * 8 + (lane & 3) * 2;
                sv[n][0] *= SC; sv[n][1] *= SC; sv[n][2] *= SC; sv[n][3] *= SC;
                if (needmask) {
                    if (j     > rlo) sv[n][0] = -1e30f;
                    if (j + 1 > rlo) sv[n][1] = -1e30f;
                    if (j     > rhi) sv[n][2] = -1e30f;
                    if (j + 1 > rhi) sv[n][3] = -1e30f;
                }
                mx0 = fmaxf(mx0, fmaxf(sv[n][0], sv[n][1]));
                mx1 = fmaxf(mx1, fmaxf(sv[n][2], sv[n][3]));
            }
            mx0 = fmaxf(mx0, __shfl_xor_sync(0xffffffffu, mx0, 1));
            mx0 = fmaxf(mx0, __shfl_xor_sync(0xffffffffu, mx0, 2));
            mx1 = fmaxf(mx1, __shfl_xor_sync(0xffffffffu, mx1, 1));
            mx1 = fmaxf(mx1, __shfl_xor_sync(0xffffffffu, mx1, 2));
            const float a0 = ex2f(m0 - mx0);
            const float a1 = ex2f(m1 - mx1);
            m0 = mx0; m1 = mx1;

            float sum0 = 0.f, sum1 = 0.f;
            #pragma unroll
            for (int n = 0; n < 8; n++) {
                sv[n][0] = ex2f(sv[n][0] - mx0);
                sv[n][1] = ex2f(sv[n][1] - mx0);
                sv[n][2] = ex2f(sv[n][2] - mx1);
                sv[n][3] = ex2f(sv[n][3] - mx1);
                sum0 += sv[n][0] + sv[n][1];
                sum1 += sv[n][2] + sv[n][3];
            }
            l0 = l0 * a0 + sum0;
            l1 = l1 * a1 + sum1;
            #pragma unroll
            for (int n = 0; n < 8; n++) {
                o[n][0] *= a0; o[n][1] *= a0; o[n][2] *= a1; o[n][3] *= a1;
            }

            uint32_t ph_[4][4], pl_[4][4];
            #pragma unroll
            for (int kc = 0; kc < 4; kc++) {
                psplit(sv[2 * kc][0],     sv[2 * kc][1],     ph_[kc][0], pl_[kc][0]);
                psplit(sv[2 * kc][2],     sv[2 * kc][3],     ph_[kc][1], pl_[kc][1]);
                psplit(sv[2 * kc + 1][0], sv[2 * kc + 1][1], ph_[kc][2], pl_[kc][2]);
                psplit(sv[2 * kc + 1][2], sv[2 * kc + 1][3], ph_[kc][3], pl_[kc][3]);
            }

            // O += P V
            #pragma unroll
            for (int kc = 0; kc < 4; kc++) {
                const int tk = kc >> 1;
                uint32_t vh[8][2], vl[8][2];
                #pragma unroll
                for (int p = 0; p < 4; p++) {
                    int r = p * 16 + (lane & 7) + ((lane >> 4) & 1) * 8;
                    int c = (kc & 1) * 2 + ((lane >> 3) & 1);
                    uint32_t off = (uint32_t)(tk * 4096 + r * 64
                                              + ((c ^ ((r >> 1) & 3)) << 4));
                    uint32_t tmp[4];
                    ldsm_x4(sVh + off, tmp);
                    vh[2 * p][0] = tmp[0]; vh[2 * p][1] = tmp[1];
                    vh[2 * p + 1][0] = tmp[2]; vh[2 * p + 1][1] = tmp[3];
                    ldsm_x4(sVl + off, tmp);
                    vl[2 * p][0] = tmp[0]; vl[2 * p][1] = tmp[1];
                    vl[2 * p + 1][0] = tmp[2]; vl[2 * p + 1][1] = tmp[3];
                }
                #pragma unroll
                for (int n = 0; n < 8; n++) mma_bf16(o[n], ph_[kc], vh[n]);
                #pragma unroll
                for (int n = 0; n < 8; n++) mma_bf16(o[n], ph_[kc], vl[n]);
                #pragma unroll
                for (int n = 0; n < 8; n++) mma_bf16(o[n], pl_[kc], vh[n]);
            }
        }
        __syncthreads();   // all warps done reading stage s before its reload
    }

    l0 += __shfl_xor_sync(0xffffffffu, l0, 1);
    l0 += __shfl_xor_sync(0xffffffffu, l0, 2);
    l1 += __shfl_xor_sync(0xffffffffu, l1, 1);
    l1 += __shfl_xor_sync(0xffffffffu, l1, 2);
    const float inv0 = 1.f / l0;
    const float inv1 = 1.f / l1;

    // epilogue: split-store into TILED GEMM layout (rows = b*T+t, cols = h*64+d)
    const int b = bh >> 4, h = bh & 15;
    const int r0 = b * T_ + q0 + w * 16 + (lane >> 2);
    const int r1 = r0 + 8;
    #pragma unroll
    for (int n = 0; n < 8; n++) {
        int cglob = h * HD + n * 8 + (lane & 3) * 2;
        uint32_t hh, ll;
        size_t o0 = tiled_off(8192, r0, cglob);
        psplit(o[n][0] * inv0, o[n][1] * inv0, hh, ll);
        *(uint32_t*)(out_hi + o0) = hh;
        *(uint32_t*)(out_lo + o0) = ll;
        size_t o1 = tiled_off(8192, r1, cglob);
        psplit(o[n][2] * inv1, o[n][3] * inv1, hh, ll);
        *(uint32_t*)(out_hi + o1) = hh;
        *(uint32_t*)(out_lo + o1) = ll;
    }
}

// =============================================================================
extern "C" void kernel_launch(void* const* d_in, const int* in_sizes, int n_in,
                              void* d_out, int out_size)
{
    (void)in_sizes; (void)n_in; (void)out_size;
    const float* x  = (const float*)d_in[0];
    const float* wq = (const float*)d_in[1];
    const float* bq = (const float*)d_in[2];
    const float* wk = (const float*)d_in[3];
    const float* bk = (const float*)d_in[4];
    const float* wv = (const float*)d_in[5];
    const float* bv = (const float*)d_in[6];
    const float* wo = (const float*)d_in[7];
    const float* bo = (const float*)d_in[8];
    float* out = (float*)d_out;

    __nv_bfloat16 *ahi, *alo, *whi, *wlo;
    __nv_bfloat16 *qhi, *qlo, *khi, *klo, *vthi, *vtlo;
    cudaGetSymbolAddress((void**)&ahi,  g_ahi);
    cudaGetSymbolAddress((void**)&alo,  g_alo);
    cudaGetSymbolAddress((void**)&whi,  g_whi);
    cudaGetSymbolAddress((void**)&wlo,  g_wlo);
    cudaGetSymbolAddress((void**)&qhi,  g_qhi);
    cudaGetSymbolAddress((void**)&qlo,  g_qlo);
    cudaGetSymbolAddress((void**)&khi,  g_khi);
    cudaGetSymbolAddress((void**)&klo,  g_klo);
    cudaGetSymbolAddress((void**)&vthi, g_vthi);
    cudaGetSymbolAddress((void**)&vtlo, g_vtlo);

    const int nW = C_ * C_;

    split_all<<<12288, 256>>>(x, wq, wk, wv, wo, ahi, alo, whi, wlo);

    cudaFuncSetAttribute(gemm_qkv, cudaFuncAttributeMaxDynamicSharedMemorySize, GEMM_SMEM);
    cudaFuncSetAttribute(gemm_out, cudaFuncAttributeMaxDynamicSharedMemorySize, GEMM_SMEM);
    cudaFuncSetAttribute(attn_tc,  cudaFuncAttributeMaxDynamicSharedMemorySize, ATT_SMEM);

    gemm_qkv<<<dim3(C_ / 128, M_ / 128, 3), 256, GEMM_SMEM>>>(
        ahi, alo, whi, wlo, bq, bk, bv, qhi, qlo, khi, klo, vthi, vtlo);

    attn_tc<<<dim3(B_ * H_, T_ / 128), 256, ATT_SMEM>>>(qhi, qlo, khi, klo,
                                                        vthi, vtlo, ahi, alo);

    gemm_out<<<dim3(C_ / 128, M_ / 128), 256, GEMM_SMEM>>>(
        ahi, alo, whi + 3 * nW, wlo + 3 * nW, bo, out);
}

// round 16
// speedup vs baseline: 1.0691x; 1.0412x over previous
#include <cuda_runtime.h>
#include <cuda_bf16.h>
#include <math.h>
#include <stdint.h>

// Problem constants
constexpr int B_  = 4;
constexpr int T_  = 2048;
constexpr int C_  = 1024;
constexpr int H_  = 16;
constexpr int HD  = 64;
constexpr int M_  = B_ * T_;

// -------------------- scratch (static device allocations) --------------------
// GEMM operands + K + V^T all use the K-CHUNK-TILED, PRE-SWIZZLED layout:
//   element (row, k) -> ((k/32)*NROWS + row)*32 + (((k>>3)&3) ^ ((row>>1)&3))*8 + (k&7)
__device__ __nv_bfloat16 g_ahi[M_ * C_];     // activations (x, later attn-out)
__device__ __nv_bfloat16 g_alo[M_ * C_];
__device__ __nv_bfloat16 g_whi[4 * C_ * C_]; // weights (q,k,v,o)
__device__ __nv_bfloat16 g_wlo[4 * C_ * C_];
__device__ __nv_bfloat16 g_qhi[B_ * H_ * T_ * HD];  // [B,H,T,hd] plain
__device__ __nv_bfloat16 g_qlo[B_ * H_ * T_ * HD];
__device__ __nv_bfloat16 g_khi[B_ * H_ * T_ * HD];  // per-bh tiled: rows=T, k=hd
__device__ __nv_bfloat16 g_klo[B_ * H_ * T_ * HD];
__device__ __nv_bfloat16 g_vthi[B_ * H_ * HD * T_]; // per-bh tiled: rows=hd, k=T
__device__ __nv_bfloat16 g_vtlo[B_ * H_ * HD * T_];

// =============================================================================
// helpers (compute_103-portable)
// =============================================================================
__device__ __forceinline__ uint32_t smem_u32(const void* p) {
    uint32_t a;
    asm("{ .reg .u64 t; cvta.to.shared.u64 t, %1; cvt.u32.u64 %0, t; }"
        : "=r"(a) : "l"(p));
    return a;
}
__device__ __forceinline__ void ldsm_x4(uint32_t addr, uint32_t* r) {
    asm volatile("ldmatrix.sync.aligned.m8n8.x4.shared.b16 {%0,%1,%2,%3}, [%4];"
                 : "=r"(r[0]), "=r"(r[1]), "=r"(r[2]), "=r"(r[3]) : "r"(addr));
}
__device__ __forceinline__ void mma_bf16(float* d, const uint32_t* a, const uint32_t* b) {
    asm volatile(
        "mma.sync.aligned.m16n8k16.row.col.f32.bf16.bf16.f32 "
        "{%0,%1,%2,%3}, {%4,%5,%6,%7}, {%8,%9}, {%0,%1,%2,%3};"
        : "+f"(d[0]), "+f"(d[1]), "+f"(d[2]), "+f"(d[3])
        : "r"(a[0]), "r"(a[1]), "r"(a[2]), "r"(a[3]), "r"(b[0]), "r"(b[1]));
}
__device__ __forceinline__ void cp_async16(uint32_t dst, const void* src) {
    asm volatile("cp.async.cg.shared.global [%0], [%1], 16;" :: "r"(dst), "l"(src));
}
#define CP_ASYNC_COMMIT() asm volatile("cp.async.commit_group;" ::: "memory")
#define CP_ASYNC_WAIT(n)  asm volatile("cp.async.wait_group %0;" :: "n"(n) : "memory")

// TMA 1D bulk copy global->shared with mbarrier completion
__device__ __forceinline__ void bulk_g2s(uint32_t dst, const void* src,
                                         uint32_t bytes, uint32_t mbar) {
    asm volatile(
        "cp.async.bulk.shared::cluster.global.mbarrier::complete_tx::bytes "
        "[%0], [%1], %2, [%3];"
        :: "r"(dst), "l"(src), "r"(bytes), "r"(mbar) : "memory");
}
#define MBARRIER_INIT(mbar, count) \
    asm volatile("mbarrier.init.shared.b64 [%0], %1;" \
                 :: "r"((uint32_t)(mbar)), "r"((uint32_t)(count)) : "memory")
#define MBARRIER_EXPECT_TX(mbar, bytes) \
    asm volatile("mbarrier.arrive.expect_tx.shared.b64 _, [%0], %1;" \
                 :: "r"((uint32_t)(mbar)), "r"((uint32_t)(bytes)) : "memory")
#define MBARRIER_ARRIVE(mbar) \
    asm volatile("mbarrier.arrive.release.cta.shared::cta.b64 _, [%0];" \
                 :: "r"((uint32_t)(mbar)) : "memory")
#define MBARRIER_WAIT_PARITY(mbar_addr, phase_parity) do { \
    uint32_t _mbar = (uint32_t)(mbar_addr); \
    uint32_t _parity = (uint32_t)(phase_parity); \
    uint32_t _done; \
    asm volatile( \
        "{\n\t.reg .pred p;\n\t" \
        "mbarrier.try_wait.parity.acquire.cta.shared::cta.b64 p, [%1], %2;\n\t" \
        "selp.b32 %0, 1, 0, p;\n\t}" \
        : "=r"(_done) : "r"(_mbar), "r"(_parity) : "memory"); \
    if (!_done) { \
        asm volatile( \
            "{\n\t.reg .pred P1;\n\t" \
            "WAIT_LOOP_%=:\n\t" \
            "mbarrier.try_wait.parity.acquire.cta.shared::cta.b64 P1, [%0], %1, 0x989680;\n\t" \
            "@P1 bra.uni WAIT_DONE_%=;\n\t" \
            "bra.uni WAIT_LOOP_%=;\n\t" \
            "WAIT_DONE_%=:\n\t}" \
            :: "r"(_mbar), "r"(_parity) : "memory"); \
    } \
} while (0)

__device__ __forceinline__ float ex2f(float x) {
    float y;
    asm("ex2.approx.ftz.f32 %0, %1;" : "=f"(y) : "f"(x));
    return y;
}
// pack (x,y) -> bf16x2 hi + bf16x2 lo residual
__device__ __forceinline__ void psplit(float x, float y, uint32_t& hi, uint32_t& lo) {
    __nv_bfloat162 h = __floats2bfloat162_rn(x, y);
    float rx = x - __bfloat162float(h.x);
    float ry = y - __bfloat162float(h.y);
    __nv_bfloat162 l = __floats2bfloat162_rn(rx, ry);
    hi = *(uint32_t*)&h;
    lo = *(uint32_t*)&l;
}

// tiled-layout element offset
__device__ __forceinline__ size_t tiled_off(int nrows, int row, int k) {
    int tk = k >> 5;
    int c  = (k >> 3) & 3;
    int cs = c ^ ((row >> 1) & 3);
    return ((size_t)(tk * nrows + row)) * 32 + cs * 8 + (k & 7);
}

// =============================================================================
// fused split: fp32 -> bf16 hi+lo, written into the tiled GEMM layout.
// =============================================================================
__global__ __launch_bounds__(256) void split_all(
    const float* __restrict__ x,
    const float* __restrict__ wq, const float* __restrict__ wk,
    const float* __restrict__ wv, const float* __restrict__ wo,
    __nv_bfloat16* __restrict__ ahi, __nv_bfloat16* __restrict__ alo,
    __nv_bfloat16* __restrict__ whi, __nv_bfloat16* __restrict__ wlo)
{
    const int nW = C_ * C_;
    int blk = blockIdx.x;
    const float* src;
    __nv_bfloat16 *hi, *lo;
    int base, nrows;
    if (blk < 8192) {
        src = x; hi = ahi; lo = alo; base = blk; nrows = 8192;
    } else {
        int r = blk - 8192;
        int ws = r >> 10;
        base = r & 1023;
        src = (ws == 0) ? wq : (ws == 1) ? wk : (ws == 2) ? wv : wo;
        hi = whi + (size_t)ws * nW;
        lo = wlo + (size_t)ws * nW;
        nrows = 1024;
    }
    int i = (base * 256 + threadIdx.x) * 4;
    int row = i >> 10;
    int k   = i & 1023;
    float4 v = *(const float4*)(src + i);
    uint32_t h0, l0, h1, l1;
    psplit(v.x, v.y, h0, l0);
    psplit(v.z, v.w, h1, l1);
    size_t off = tiled_off(nrows, row, k);
    *(uint32_t*)(hi + off)     = h0;
    *(uint32_t*)(hi + off + 2) = h1;
    *(uint32_t*)(lo + off)     = l0;
    *(uint32_t*)(lo + off + 2) = l1;
}

// =============================================================================
// GEMM mainloop: 2-stage TMA bulk pipeline, producer/consumer mbarriers
// (round-14 exact — winning config).
// =============================================================================
constexpr int TILE_B      = 128 * 64;                // 8192 bytes per operand tile
constexpr int STAGE_BYTES = 4 * TILE_B;              // 32768
constexpr int GEMM_SMEM   = 2 * STAGE_BYTES + 64;    // + mbarriers

__device__ __forceinline__ void gemm_issue_stage(
    uint32_t st, uint32_t mbar,
    const __nv_bfloat16* __restrict__ Ahi, const __nv_bfloat16* __restrict__ Alo,
    const __nv_bfloat16* __restrict__ Whi, const __nv_bfloat16* __restrict__ Wlo,
    int bm, int bn, int tk)
{
    MBARRIER_EXPECT_TX(mbar, STAGE_BYTES);
    bulk_g2s(st,              Ahi + (size_t)(tk * 8192 + bm) * 32, TILE_B, mbar);
    bulk_g2s(st + TILE_B,     Alo + (size_t)(tk * 8192 + bm) * 32, TILE_B, mbar);
    bulk_g2s(st + 2 * TILE_B, Whi + (size_t)(tk * 1024 + bn) * 32, TILE_B, mbar);
    bulk_g2s(st + 3 * TILE_B, Wlo + (size_t)(tk * 1024 + bn) * 32, TILE_B, mbar);
}

__device__ __forceinline__ void gemm_mainloop(
    uint32_t sbase,
    const __nv_bfloat16* __restrict__ Ahi, const __nv_bfloat16* __restrict__ Alo,
    const __nv_bfloat16* __restrict__ Whi, const __nv_bfloat16* __restrict__ Wlo,
    int bm, int bn, int tid, float acc[2][8][4])
{
    const int lane = tid & 31;
    const int w    = tid >> 5;
    const int wm0  = (w & 3) * 32;
    const int wn0  = (w >> 2) * 64;
    constexpr int NC = C_ / 32;

    const uint32_t mbF0 = sbase + 2 * STAGE_BYTES;
    const uint32_t mbF1 = mbF0 + 8;
    const uint32_t mbE0 = mbF0 + 16;
    const uint32_t mbE1 = mbF0 + 24;

    if (tid == 0) {
        MBARRIER_INIT(mbF0, 1); MBARRIER_INIT(mbF1, 1);
        MBARRIER_INIT(mbE0, 8); MBARRIER_INIT(mbE1, 8);
    }
    __syncthreads();

    if (tid == 0) {
        gemm_issue_stage(sbase,               mbF0, Ahi, Alo, Whi, Wlo, bm, bn, 0);
        gemm_issue_stage(sbase + STAGE_BYTES, mbF1, Ahi, Alo, Whi, Wlo, bm, bn, 1);
    }

    int phF0 = 0, phF1 = 0, phE0 = 0, phE1 = 0;

    for (int ck = 0; ck < NC; ck++) {
        const int s = ck & 1;

        if (tid == 0 && ck >= 1 && ck + 1 < NC) {
            if (s == 0) { MBARRIER_WAIT_PARITY(mbE1, phE1); phE1 ^= 1; }
            else        { MBARRIER_WAIT_PARITY(mbE0, phE0); phE0 ^= 1; }
            const uint32_t st   = sbase + (uint32_t)(s ^ 1) * STAGE_BYTES;
            const uint32_t mbar = (s == 0) ? mbF1 : mbF0;
            gemm_issue_stage(st, mbar, Ahi, Alo, Whi, Wlo, bm, bn, ck + 1);
        }

        if (s == 0) { MBARRIER_WAIT_PARITY(mbF0, phF0); phF0 ^= 1; }
        else        { MBARRIER_WAIT_PARITY(mbF1, phF1); phF1 ^= 1; }

        const uint32_t st  = sbase + (uint32_t)s * STAGE_BYTES;
        const uint32_t sAh = st;
        const uint32_t sAl = st + TILE_B;
        const uint32_t sWh = st + 2 * TILE_B;
        const uint32_t sWl = st + 3 * TILE_B;

        #pragma unroll
        for (int kk = 0; kk < 2; kk++) {
            uint32_t ah[2][4], al[2][4];
            #pragma unroll
            for (int mi = 0; mi < 2; mi++) {
                int r = wm0 + mi * 16 + (lane & 15);
                int c = kk * 2 + (lane >> 4);
                uint32_t off = (uint32_t)(r * 64 + ((c ^ ((r >> 1) & 3)) << 4));
                ldsm_x4(sAh + off, ah[mi]);
                ldsm_x4(sAl + off, al[mi]);
            }
            #pragma unroll
            for (int p = 0; p < 4; p++) {
                int r = wn0 + p * 16 + (lane & 7) + ((lane >> 4) & 1) * 8;
                int c = kk * 2 + ((lane >> 3) & 1);
                uint32_t off = (uint32_t)(r * 64 + ((c ^ ((r >> 1) & 3)) << 4));
                uint32_t wh[4], wl[4];
                ldsm_x4(sWh + off, wh);
                ldsm_x4(sWl + off, wl);
                #pragma unroll
                for (int mi = 0; mi < 2; mi++) {
                    mma_bf16(acc[mi][2 * p],     ah[mi], wh + 0);
                    mma_bf16(acc[mi][2 * p + 1], ah[mi], wh + 2);
                    mma_bf16(acc[mi][2 * p],     ah[mi], wl + 0);
                    mma_bf16(acc[mi][2 * p + 1], ah[mi], wl + 2);
                    mma_bf16(acc[mi][2 * p],     al[mi], wh + 0);
                    mma_bf16(acc[mi][2 * p + 1], al[mi], wh + 2);
                }
            }
        }

        if (lane == 0) {
            if (s == 0) MBARRIER_ARRIVE(mbE0);
            else        MBARRIER_ARRIVE(mbE1);
        }
    }
}

// ---------- fused QKV projection: z selects {q,k,v} ----------
__global__ __launch_bounds__(256, 2) void gemm_qkv(
    const __nv_bfloat16* __restrict__ Ahi, const __nv_bfloat16* __restrict__ Alo,
    const __nv_bfloat16* __restrict__ Wh,  const __nv_bfloat16* __restrict__ Wl,
    const float* __restrict__ b0, const float* __restrict__ b1,
    const float* __restrict__ b2,
    __nv_bfloat16* __restrict__ qh, __nv_bfloat16* __restrict__ ql,
    __nv_bfloat16* __restrict__ kh, __nv_bfloat16* __restrict__ kl,
    __nv_bfloat16* __restrict__ vh, __nv_bfloat16* __restrict__ vl)
{
    extern __shared__ __align__(1024) char smem[];
    const uint32_t sbase = smem_u32(smem);
    const int tid = threadIdx.x;
    const int bm  = blockIdx.y * 128;
    const int bn  = blockIdx.x * 128;
    const int z   = blockIdx.z;
    const int nW  = C_ * C_;

    const float* bias = (z == 0) ? b0 : (z == 1) ? b1 : b2;

    float acc[2][8][4];
    #pragma unroll
    for (int mi = 0; mi < 2; mi++)
        #pragma unroll
        for (int ni = 0; ni < 8; ni++)
            #pragma unroll
            for (int t = 0; t < 4; t++) acc[mi][ni][t] = 0.f;

    gemm_mainloop(sbase, Ahi, Alo, Wh + (size_t)z * nW, Wl + (size_t)z * nW,
                  bm, bn, tid, acc);

    const int lane = tid & 31;
    const int w    = tid >> 5;
    const int wm0  = (w & 3) * 32;
    const int wn0  = (w >> 2) * 64;

    #pragma unroll
    for (int mi = 0; mi < 2; mi++) {
        #pragma unroll
        for (int ni = 0; ni < 8; ni++) {
            int row0 = bm + wm0 + mi * 16 + (lane >> 2);
            int col  = bn + wn0 + ni * 8 + (lane & 3) * 2;
            float bb0 = bias[col], bb1 = bias[col + 1];
            float v00 = acc[mi][ni][0] + bb0, v01 = acc[mi][ni][1] + bb1;
            float v10 = acc[mi][ni][2] + bb0, v11 = acc[mi][ni][3] + bb1;
            int h = col >> 6, d = col & 63;
            if (z == 0) {   // Q plain [B,H,T,hd]
                uint32_t hh, ll;
                {
                    int b = row0 >> 11, t = row0 & 2047;
                    size_t o = ((size_t)((b * H_ + h) * T_ + t)) * HD + d;
                    psplit(v00, v01, hh, ll);
                    *(uint32_t*)(qh + o) = hh; *(uint32_t*)(ql + o) = ll;
                }
                {
                    int r1 = row0 + 8;
                    int b = r1 >> 11, t = r1 & 2047;
                    size_t o = ((size_t)((b * H_ + h) * T_ + t)) * HD + d;
                    psplit(v10, v11, hh, ll);
                    *(uint32_t*)(qh + o) = hh; *(uint32_t*)(ql + o) = ll;
                }
            } else if (z == 1) {   // K tiled per bh: rows=T, k=hd
                uint32_t hh, ll;
                {
                    int b = row0 >> 11, t = row0 & 2047;
                    size_t o = (size_t)(b * H_ + h) * T_ * HD + tiled_off(T_, t, d);
                    psplit(v00, v01, hh, ll);
                    *(uint32_t*)(kh + o) = hh; *(uint32_t*)(kl + o) = ll;
                }
                {
                    int r1 = row0 + 8;
                    int b = r1 >> 11, t = r1 & 2047;
                    size_t o = (size_t)(b * H_ + h) * T_ * HD + tiled_off(T_, t, d);
                    psplit(v10, v11, hh, ll);
                    *(uint32_t*)(kh + o) = hh; *(uint32_t*)(kl + o) = ll;
                }
            } else {       // V^T tiled per bh: rows=hd, k=T
                int b = row0 >> 11, t = row0 & 2047;
                size_t bb = (size_t)(b * H_ + h) * HD * T_;
                __nv_bfloat16 h00 = __float2bfloat16_rn(v00);
                __nv_bfloat16 h01 = __float2bfloat16_rn(v01);
                __nv_bfloat16 h10 = __float2bfloat16_rn(v10);
                __nv_bfloat16 h11 = __float2bfloat16_rn(v11);
                size_t o00 = bb + tiled_off(HD, d,     t);
                size_t o01 = bb + tiled_off(HD, d + 1, t);
                size_t o10 = bb + tiled_off(HD, d,     t + 8);
                size_t o11 = bb + tiled_off(HD, d + 1, t + 8);
                vh[o00] = h00; vh[o01] = h01; vh[o10] = h10; vh[o11] = h11;
                vl[o00] = __float2bfloat16_rn(v00 - __bfloat162float(h00));
                vl[o01] = __float2bfloat16_rn(v01 - __bfloat162float(h01));
                vl[o10] = __float2bfloat16_rn(v10 - __bfloat162float(h10));
                vl[o11] = __float2bfloat16_rn(v11 - __bfloat162float(h11));
            }
        }
    }
}

// ---------- O-projection: fp32 row-major output ----------
__global__ __launch_bounds__(256, 2) void gemm_out(
    const __nv_bfloat16* __restrict__ Ahi, const __nv_bfloat16* __restrict__ Alo,
    const __nv_bfloat16* __restrict__ Whi, const __nv_bfloat16* __restrict__ Wlo,
    const float* __restrict__ bias, float* __restrict__ out)
{
    extern __shared__ __align__(1024) char smem[];
    const uint32_t sbase = smem_u32(smem);
    const int tid = threadIdx.x;
    const int bm  = blockIdx.y * 128;
    const int bn  = blockIdx.x * 128;

    float acc[2][8][4];
    #pragma unroll
    for (int mi = 0; mi < 2; mi++)
        #pragma unroll
        for (int ni = 0; ni < 8; ni++)
            #pragma unroll
            for (int t = 0; t < 4; t++) acc[mi][ni][t] = 0.f;

    gemm_mainloop(sbase, Ahi, Alo, Whi, Wlo, bm, bn, tid, acc);

    const int lane = tid & 31;
    const int w    = tid >> 5;
    const int wm0  = (w & 3) * 32;
    const int wn0  = (w >> 2) * 64;

    #pragma unroll
    for (int mi = 0; mi < 2; mi++) {
        #pragma unroll
        for (int ni = 0; ni < 8; ni++) {
            int row0 = bm + wm0 + mi * 16 + (lane >> 2);
            int col  = bn + wn0 + ni * 8 + (lane & 3) * 2;
            float b0 = bias[col], b1 = bias[col + 1];
            float2 a; a.x = acc[mi][ni][0] + b0; a.y = acc[mi][ni][1] + b1;
            float2 c; c.x = acc[mi][ni][2] + b0; c.y = acc[mi][ni][3] + b1;
            *(float2*)&out[(size_t)row0 * C_ + col]       = a;
            *(float2*)&out[(size_t)(row0 + 8) * C_ + col] = c;
        }
    }
}

// =============================================================================
// Tensor-core flash attention (causal), 2-stage TMA-bulk KV pipeline with
// producer/consumer mbarriers, 2 CTAs/SM, per-p fragment loads (low regs).
// =============================================================================
constexpr int ARS       = 72;                 // Q smem row stride (bf16)
constexpr int QS_BYTES  = 128 * ARS * 2;      // 18432
constexpr int KV_TILE   = 64 * 64 * 2;        // 8192 bytes per operand tile
constexpr int KV_STAGE  = 4 * KV_TILE;        // 32768 (Khi,Klo,Vhi,Vlo)
constexpr int ATT_SMEM  = 2 * QS_BYTES + 2 * KV_STAGE + 64;   // 102464

__device__ __forceinline__ void att_issue_kv(
    uint32_t st, uint32_t mbar,
    const __nv_bfloat16* __restrict__ Kh, const __nv_bfloat16* __restrict__ Kl,
    const __nv_bfloat16* __restrict__ Vh, const __nv_bfloat16* __restrict__ Vl,
    int kt)
{
    const int k0 = kt * 64;
    MBARRIER_EXPECT_TX(mbar, KV_STAGE);
    #pragma unroll
    for (int tk = 0; tk < 2; tk++) {
        bulk_g2s(st + 0 * KV_TILE + tk * 4096, Kh + ((size_t)tk * T_ + k0) * 32, 4096, mbar);
        bulk_g2s(st + 1 * KV_TILE + tk * 4096, Kl + ((size_t)tk * T_ + k0) * 32, 4096, mbar);
        bulk_g2s(st + 2 * KV_TILE + tk * 4096, Vh + ((size_t)(2 * kt + tk) * 64) * 32, 4096, mbar);
        bulk_g2s(st + 3 * KV_TILE + tk * 4096, Vl + ((size_t)(2 * kt + tk) * 64) * 32, 4096, mbar);
    }
}

__global__ __launch_bounds__(256, 2) void attn_tc(
    const __nv_bfloat16* __restrict__ qhi, const __nv_bfloat16* __restrict__ qlo,
    const __nv_bfloat16* __restrict__ khi, const __nv_bfloat16* __restrict__ klo,
    const __nv_bfloat16* __restrict__ vthi, const __nv_bfloat16* __restrict__ vtlo,
    __nv_bfloat16* __restrict__ out_hi, __nv_bfloat16* __restrict__ out_lo)
{
    extern __shared__ __align__(1024) char smem[];
    const uint32_t sb  = smem_u32(smem);
    const uint32_t sQh = sb, sQl = sb + QS_BYTES;
    const uint32_t kvb = sb + 2 * QS_BYTES;
    const uint32_t mbF0 = kvb + 2 * KV_STAGE;
    const uint32_t mbF1 = mbF0 + 8;
    const uint32_t mbE0 = mbF0 + 16;
    const uint32_t mbE1 = mbF0 + 24;
    const int tid  = threadIdx.x;
    const int lane = tid & 31;
    const int w    = tid >> 5;
    const int bh   = blockIdx.x;
    const int qi   = (int)gridDim.y - 1 - (int)blockIdx.y;  // longest first
    const int q0   = qi * 128;
    const int ktmax = 2 * qi + 1;
    const float SC = 0.18033688011112042f;   // hd^-0.5 * log2(e)

    const __nv_bfloat16* Kh = khi  + (size_t)bh * T_ * HD;
    const __nv_bfloat16* Kl = klo  + (size_t)bh * T_ * HD;
    const __nv_bfloat16* Vh = vthi + (size_t)bh * HD * T_;
    const __nv_bfloat16* Vl = vtlo + (size_t)bh * HD * T_;

    // Q prologue loads (plain layout -> ARS smem)
    #pragma unroll
    for (int it = 0; it < 4; it++) {
        int id  = tid + it * 256;
        int row = id >> 3;
        int ch  = id & 7;
        uint32_t so = (uint32_t)(row * (ARS * 2) + ch * 16);
        size_t go = ((size_t)(bh * T_ + q0 + row) * HD + ch * 8) * 2;
        cp_async16(sQh + so, (const char*)qhi + go);
        cp_async16(sQl + so, (const char*)qlo + go);
    }
    CP_ASYNC_COMMIT();

    if (tid == 0) {
        MBARRIER_INIT(mbF0, 1); MBARRIER_INIT(mbF1, 1);
        MBARRIER_INIT(mbE0, 8); MBARRIER_INIT(mbE1, 8);
    }
    __syncthreads();

    // KV tiles 0 and 1 (ktmax >= 1 always)
    if (tid == 0) {
        att_issue_kv(kvb,            mbF0, Kh, Kl, Vh, Vl, 0);
        att_issue_kv(kvb + KV_STAGE, mbF1, Kh, Kl, Vh, Vl, 1);
    }

    // Q ready CTA-wide, preload Q fragments once
    CP_ASYNC_WAIT(0);
    __syncthreads();
    uint32_t qfh[4][4], qfl[4][4];
    #pragma unroll
    for (int kc = 0; kc < 4; kc++) {
        uint32_t off = (uint32_t)((w * 16 + (lane & 15)) * (ARS * 2)
                                  + kc * 32 + ((lane >> 4) << 4));
        ldsm_x4(sQh + off, qfh[kc]);
        ldsm_x4(sQl + off, qfl[kc]);
    }

    float o[8][4];
    #pragma unroll
    for (int n = 0; n < 8; n++)
        #pragma unroll
        for (int t = 0; t < 4; t++) o[n][t] = 0.f;
    float m0 = -1e30f, m1 = -1e30f, l0 = 0.f, l1 = 0.f;

    const int rlo_base = q0 + w * 16 + (lane >> 2);
    int phF0 = 0, phF1 = 0, phE0 = 0, phE1 = 0;

    for (int kt = 0; kt <= ktmax; kt++) {
        const int s = kt & 1;

        // producer: refill stage s^1 (emptied at end of iter kt-1) with kt+1
        if (tid == 0 && kt >= 1 && kt + 1 <= ktmax) {
            if (s == 0) { MBARRIER_WAIT_PARITY(mbE1, phE1); phE1 ^= 1; }
            else        { MBARRIER_WAIT_PARITY(mbE0, phE0); phE0 ^= 1; }
            const uint32_t st   = kvb + (uint32_t)(s ^ 1) * KV_STAGE;
            const uint32_t mbar = (s == 0) ? mbF1 : mbF0;
            att_issue_kv(st, mbar, Kh, Kl, Vh, Vl, kt + 1);
        }

        // consumer: wait data (per-thread acquire, no CTA rendezvous)
        if (s == 0) { MBARRIER_WAIT_PARITY(mbF0, phF0); phF0 ^= 1; }
        else        { MBARRIER_WAIT_PARITY(mbF1, phF1); phF1 ^= 1; }

        bool active = (kt * 64 <= q0 + w * 16 + 15);

        if (active) {
            const uint32_t st  = kvb + (uint32_t)s * KV_STAGE;
            const uint32_t sKh = st, sKl = st + KV_TILE;
            const uint32_t sVh = st + 2 * KV_TILE, sVl = st + 3 * KV_TILE;

            float sv[8][4];
            #pragma unroll
            for (int n = 0; n < 8; n++)
                #pragma unroll
                for (int t = 0; t < 4; t++) sv[n][t] = 0.f;

            // S = Q K^T (per-p fragment loads — low register pressure)
            #pragma unroll
            for (int kc = 0; kc < 4; kc++) {
                const int tk = kc >> 1;
                #pragma unroll
                for (int p = 0; p < 4; p++) {
                    int r = p * 16 + (lane & 7) + ((lane >> 4) & 1) * 8;
                    int c = (kc & 1) * 2 + ((lane >> 3) & 1);
                    uint32_t off = (uint32_t)(tk * 4096 + r * 64
                                              + ((c ^ ((r >> 1) & 3)) << 4));
                    uint32_t khf[4], klf[4];
                    ldsm_x4(sKh + off, khf);
                    ldsm_x4(sKl + off, klf);
                    mma_bf16(sv[2 * p],     qfh[kc], khf + 0);
                    mma_bf16(sv[2 * p + 1], qfh[kc], khf + 2);
                    mma_bf16(sv[2 * p],     qfh[kc], klf + 0);
                    mma_bf16(sv[2 * p + 1], qfh[kc], klf + 2);
                    mma_bf16(sv[2 * p],     qfl[kc], khf + 0);
                    mma_bf16(sv[2 * p + 1], qfl[kc], khf + 2);
                }
            }

            const int rlo = rlo_base;
            const int rhi = rlo + 8;
            const bool needmask = (kt * 64 + 63 > q0 + w * 16);
            float mx0 = m0, mx1 = m1;
            #pragma unroll
            for (int n = 0; n < 8; n++) {
                int j = kt * 64 + n * 8 + (lane & 3) * 2;
                sv[n][0] *= SC; sv[n][1] *= SC; sv[n][2] *= SC; sv[n][3] *= SC;
                if (needmask) {
                    if (j     > rlo) sv[n][0] = -1e30f;
                    if (j + 1 > rlo) sv[n][1] = -1e30f;
                    if (j     > rhi) sv[n][2] = -1e30f;
                    if (j + 1 > rhi) sv[n][3] = -1e30f;
                }
                mx0 = fmaxf(mx0, fmaxf(sv[n][0], sv[n][1]));
                mx1 = fmaxf(mx1, fmaxf(sv[n][2], sv[n][3]));
            }
            mx0 = fmaxf(mx0, __shfl_xor_sync(0xffffffffu, mx0, 1));
            mx0 = fmaxf(mx0, __shfl_xor_sync(0xffffffffu, mx0, 2));
            mx1 = fmaxf(mx1, __shfl_xor_sync(0xffffffffu, mx1, 1));
            mx1 = fmaxf(mx1, __shfl_xor_sync(0xffffffffu, mx1, 2));
            const float a0 = ex2f(m0 - mx0);
            const float a1 = ex2f(m1 - mx1);
            m0 = mx0; m1 = mx1;

            float sum0 = 0.f, sum1 = 0.f;
            #pragma unroll
            for (int n = 0; n < 8; n++) {
                sv[n][0] = ex2f(sv[n][0] - mx0);
                sv[n][1] = ex2f(sv[n][1] - mx0);
                sv[n][2] = ex2f(sv[n][2] - mx1);
                sv[n][3] = ex2f(sv[n][3] - mx1);
                sum0 += sv[n][0] + sv[n][1];
                sum1 += sv[n][2] + sv[n][3];
            }
            l0 = l0 * a0 + sum0;
            l1 = l1 * a1 + sum1;
            #pragma unroll
            for (int n = 0; n < 8; n++) {
                o[n][0] *= a0; o[n][1] *= a0; o[n][2] *= a1; o[n][3] *= a1;
            }

            uint32_t ph_[4][4], pl_[4][4];
            #pragma unroll
            for (int kc = 0; kc < 4; kc++) {
                psplit(sv[2 * kc][0],     sv[2 * kc][1],     ph_[kc][0], pl_[kc][0]);
                psplit(sv[2 * kc][2],     sv[2 * kc][3],     ph_[kc][1], pl_[kc][1]);
                psplit(sv[2 * kc + 1][0], sv[2 * kc + 1][1], ph_[kc][2], pl_[kc][2]);
                psplit(sv[2 * kc + 1][2], sv[2 * kc + 1][3], ph_[kc][3], pl_[kc][3]);
            }

            // O += P V (per-p fragment loads)
            #pragma unroll
            for (int kc = 0; kc < 4; kc++) {
                const int tk = kc >> 1;
                #pragma unroll
                for (int p = 0; p < 4; p++) {
                    int r = p * 16 + (lane & 7) + ((lane >> 4) & 1) * 8;
                    int c = (kc & 1) * 2 + ((lane >> 3) & 1);
                    uint32_t off = (uint32_t)(tk * 4096 + r * 64
                                              + ((c ^ ((r >> 1) & 3)) << 4));
                    uint32_t vhf[4], vlf[4];
                    ldsm_x4(sVh + off, vhf);
                    ldsm_x4(sVl + off, vlf);
                    mma_bf16(o[2 * p],     ph_[kc], vhf + 0);
                    mma_bf16(o[2 * p + 1], ph_[kc], vhf + 2);
                    mma_bf16(o[2 * p],     ph_[kc], vlf + 0);
                    mma_bf16(o[2 * p + 1], ph_[kc], vlf + 2);
                    mma_bf16(o[2 * p],     pl_[kc], vhf + 0);
                    mma_bf16(o[2 * p + 1], pl_[kc], vhf + 2);
                }
            }
        }

        // this warp is done reading stage s
        if (lane == 0) {
            if (s == 0) MBARRIER_ARRIVE(mbE0);
            else        MBARRIER_ARRIVE(mbE1);
        }
    }

    l0 += __shfl_xor_sync(0xffffffffu, l0, 1);
    l0 += __shfl_xor_sync(0xffffffffu, l0, 2);
    l1 += __shfl_xor_sync(0xffffffffu, l1, 1);
    l1 += __shfl_xor_sync(0xffffffffu, l1, 2);
    const float inv0 = 1.f / l0;
    const float inv1 = 1.f / l1;

    // epilogue: split-store into TILED GEMM layout (rows = b*T+t, cols = h*64+d)
    const int b = bh >> 4, h = bh & 15;
    const int r0 = b * T_ + q0 + w * 16 + (lane >> 2);
    const int r1 = r0 + 8;
    #pragma unroll
    for (int n = 0; n < 8; n++) {
        int cglob = h * HD + n * 8 + (lane & 3) * 2;
        uint32_t hh, ll;
        size_t o0 = tiled_off(8192, r0, cglob);
        psplit(o[n][0] * inv0, o[n][1] * inv0, hh, ll);
        *(uint32_t*)(out_hi + o0) = hh;
        *(uint32_t*)(out_lo + o0) = ll;
        size_t o1 = tiled_off(8192, r1, cglob);
        psplit(o[n][2] * inv1, o[n][3] * inv1, hh, ll);
        *(uint32_t*)(out_hi + o1) = hh;
        *(uint32_t*)(out_lo + o1) = ll;
    }
}

// =============================================================================
extern "C" void kernel_launch(void* const* d_in, const int* in_sizes, int n_in,
                              void* d_out, int out_size)
{
    (void)in_sizes; (void)n_in; (void)out_size;
    const float* x  = (const float*)d_in[0];
    const float* wq = (const float*)d_in[1];
    const float* bq = (const float*)d_in[2];
    const float* wk = (const float*)d_in[3];
    const float* bk = (const float*)d_in[4];
    const float* wv = (const float*)d_in[5];
    const float* bv = (const float*)d_in[6];
    const float* wo = (const float*)d_in[7];
    const float* bo = (const float*)d_in[8];
    float* out = (float*)d_out;

    __nv_bfloat16 *ahi, *alo, *whi, *wlo;
    __nv_bfloat16 *qhi, *qlo, *khi, *klo, *vthi, *vtlo;
    cudaGetSymbolAddress((void**)&ahi,  g_ahi);
    cudaGetSymbolAddress((void**)&alo,  g_alo);
    cudaGetSymbolAddress((void**)&whi,  g_whi);
    cudaGetSymbolAddress((void**)&wlo,  g_wlo);
    cudaGetSymbolAddress((void**)&qhi,  g_qhi);
    cudaGetSymbolAddress((void**)&qlo,  g_qlo);
    cudaGetSymbolAddress((void**)&khi,  g_khi);
    cudaGetSymbolAddress((void**)&klo,  g_klo);
    cudaGetSymbolAddress((void**)&vthi, g_vthi);
    cudaGetSymbolAddress((void**)&vtlo, g_vtlo);

    const int nW = C_ * C_;

    split_all<<<12288, 256>>>(x, wq, wk, wv, wo, ahi, alo, whi, wlo);

    cudaFuncSetAttribute(gemm_qkv, cudaFuncAttributeMaxDynamicSharedMemorySize, GEMM_SMEM);
    cudaFuncSetAttribute(gemm_out, cudaFuncAttributeMaxDynamicSharedMemorySize, GEMM_SMEM);
    cudaFuncSetAttribute(attn_tc,  cudaFuncAttributeMaxDynamicSharedMemorySize, ATT_SMEM);

    gemm_qkv<<<dim3(C_ / 128, M_ / 128, 3), 256, GEMM_SMEM>>>(
        ahi, alo, whi, wlo, bq, bk, bv, qhi, qlo, khi, klo, vthi, vtlo);

    attn_tc<<<dim3(B_ * H_, T_ / 128), 256, ATT_SMEM>>>(qhi, qlo, khi, klo,
                                                        vthi, vtlo, ahi, alo);

    gemm_out<<<dim3(C_ / 128, M_ / 128), 256, GEMM_SMEM>>>(
        ahi, alo, whi + 3 * nW, wlo + 3 * nW, bo, out);
}